// round 5
// baseline (speedup 1.0000x reference)
#include <cuda_runtime.h>
#include <math.h>

// ---------------- problem constants ----------------
#define TROWS 131072          // B * H * W = 32 * 4096
#define DIMC  384
#define HIDC  1536
#define QKVC  1152
#define NHEAD 12
#define HDIM  32
#define NTOK  64              // tokens per window
#define NWIN  2048            // 32 * 64 windows

// ---------------- scratch (device globals; no allocation) ----------------
__device__ float g_qkv[150994944];   // TROWS * 1152
__device__ float g_attn[50331648];   // TROWS * 384
__device__ float g_tmp[50331648];    // TROWS * 384
__device__ float g_x1[50331648];     // TROWS * 384
__device__ float g_hid[201326592];   // TROWS * 1536
__device__ float g_bias16[NHEAD * 225];
__device__ float g_scale[NHEAD];
__device__ float g_qkvbias[QKVC];

// ---------------- prep: CPB table, head scales, qkv bias ----------------
__device__ __forceinline__ float cpb_norm(int c) {
    float t = (float)c * (8.0f / 7.0f);
    float s = (t > 0.f) ? 1.f : ((t < 0.f) ? -1.f : 0.f);
    return s * log2f(fabsf(t) + 1.0f) * (1.0f / 3.0f);
}

__global__ void prep_kernel(const float* __restrict__ ls,
                            const float* __restrict__ w1,
                            const float* __restrict__ b1,
                            const float* __restrict__ w2,
                            const float* __restrict__ qb,
                            const float* __restrict__ vb)
{
    int tid = threadIdx.x;
    for (int i = tid; i < QKVC; i += 256) {
        float v = 0.f;
        if (i < 384) v = qb[i];
        else if (i >= 768) v = vb[i - 768];
        g_qkvbias[i] = v;
    }
    if (tid < NHEAD) g_scale[tid] = expf(fminf(ls[tid], 4.6051701859880914f)); // ln(100)
    if (tid < 225) {
        int i = tid / 15, j = tid % 15;
        float f0 = cpb_norm(j - 7);
        float f1 = cpb_norm(i - 7);
        float acc[NHEAD];
        #pragma unroll
        for (int h = 0; h < NHEAD; h++) acc[h] = 0.f;
        for (int u = 0; u < 512; u++) {
            float hu = fmaf(f0, w1[u], fmaf(f1, w1[512 + u], b1[u]));
            hu = fmaxf(hu, 0.f);
            #pragma unroll
            for (int h = 0; h < NHEAD; h++) acc[h] = fmaf(hu, w2[u * 12 + h], acc[h]);
        }
        #pragma unroll
        for (int h = 0; h < NHEAD; h++)
            g_bias16[h * 225 + tid] = 16.f / (1.f + expf(-acc[h]));
    }
}

// ---------------- attention: one (window, head) per block ----------------
__global__ __launch_bounds__(64) void attn_kernel(const float* __restrict__ qkv,
                                                  float* __restrict__ out)
{
    __shared__ float kn[64][33];
    __shared__ float vs[64][33];
    __shared__ float bia[225];
    __shared__ int   lab[64];

    int blk  = blockIdx.x;
    int head = blk % NHEAD;
    int w    = blk / NHEAD;
    int b    = w >> 6;
    int win  = w & 63;
    int wh = win >> 3, ww = win & 7;
    int t = threadIdx.x;
    int r = t >> 3, c = t & 7;
    int hp = wh * 8 + r, wp = ww * 8 + c;
    int sh = (hp + 4) & 63, sw = (wp + 4) & 63;
    size_t row = (size_t)b * 4096 + (size_t)sh * 64 + sw;
    const float* base = qkv + row * QKVC + head * HDIM;

    int lh = (hp < 56) ? 0 : ((hp < 60) ? 1 : 2);
    int lw = (wp < 56) ? 0 : ((wp < 60) ? 1 : 2);
    lab[t] = lh * 3 + lw;

    for (int i = t; i < 225; i += 64) bia[i] = g_bias16[head * 225 + i];

    float qreg[HDIM];
    {
        float tmp[HDIM];
        float nk = 0.f;
        #pragma unroll
        for (int d4 = 0; d4 < 8; d4++) {
            float4 v4 = *(const float4*)(base + 384 + d4 * 4);
            tmp[d4*4+0] = v4.x; tmp[d4*4+1] = v4.y; tmp[d4*4+2] = v4.z; tmp[d4*4+3] = v4.w;
        }
        #pragma unroll
        for (int d = 0; d < HDIM; d++) nk = fmaf(tmp[d], tmp[d], nk);
        float invk = 1.0f / sqrtf(nk);
        #pragma unroll
        for (int d = 0; d < HDIM; d++) kn[t][d] = tmp[d] * invk;

        #pragma unroll
        for (int d4 = 0; d4 < 8; d4++) {
            float4 v4 = *(const float4*)(base + 768 + d4 * 4);
            vs[t][d4*4+0] = v4.x; vs[t][d4*4+1] = v4.y; vs[t][d4*4+2] = v4.z; vs[t][d4*4+3] = v4.w;
        }

        float nq = 0.f;
        #pragma unroll
        for (int d4 = 0; d4 < 8; d4++) {
            float4 v4 = *(const float4*)(base + d4 * 4);
            qreg[d4*4+0] = v4.x; qreg[d4*4+1] = v4.y; qreg[d4*4+2] = v4.z; qreg[d4*4+3] = v4.w;
        }
        #pragma unroll
        for (int d = 0; d < HDIM; d++) nq = fmaf(qreg[d], qreg[d], nq);
        float invq = g_scale[head] / sqrtf(nq);
        #pragma unroll
        for (int d = 0; d < HDIM; d++) qreg[d] *= invq;
    }
    __syncthreads();

    float lg[NTOK];
    float mx = -1e30f;
    int myl = lab[t];
    for (int t2 = 0; t2 < NTOK; t2++) {
        float acc = 0.f;
        #pragma unroll
        for (int d = 0; d < HDIM; d++) acc = fmaf(qreg[d], kn[t2][d], acc);
        int r2 = t2 >> 3, c2 = t2 & 7;
        acc += bia[(c - c2 + 7) * 15 + (r - r2 + 7)];
        if (myl != lab[t2]) acc -= 100.f;
        lg[t2] = acc;
        mx = fmaxf(mx, acc);
    }
    float ssum = 0.f;
    for (int t2 = 0; t2 < NTOK; t2++) {
        lg[t2] = __expf(lg[t2] - mx);
        ssum += lg[t2];
    }
    float isum = 1.0f / ssum;
    for (int t2 = 0; t2 < NTOK; t2++) lg[t2] *= isum;

    float* orow = out + row * DIMC + head * HDIM;
    for (int d = 0; d < HDIM; d++) {
        float acc = 0.f;
        for (int t2 = 0; t2 < NTOK; t2++) acc = fmaf(lg[t2], vs[t2][d], acc);
        orow[d] = acc;
    }
}

// ---------------- tf32 tensor-core GEMM, 256x128 CTA, 8 warps of 64x64 ----------------
// Fragment-ready smem layouts:
//  A: element (m,k), m in [0,256), k in [0,16):
//     group = (k>>3)*16 + (m>>4)            (32 groups of 128 words)
//     lane  = (m&7)*4 + (k&3), perm = lane ^ (lane>>2)
//     reg   = ((k>>2)&1)*2 + ((m>>3)&1)
//     word  = group*128 + perm*4 + reg      -> warp fragment = one LDS.128
//  B: element (k,n), k in [0,16), n in [0,128):
//     group = (k>>3)*16 + (n>>3)            (32 groups of 64 words)
//     lane  = (n&7)*4 + (k&3), perm = (lane ^ (lane>>2)) ^ ((k>>3)*6)
//     reg   = (k>>2)&1
//     word  = group*64 + perm*2 + reg       -> warp fragment = one LDS.64
#define PERM5(x) ((x) ^ ((x) >> 2))

__device__ __forceinline__ unsigned f2tf32(float f) {
    unsigned u;
    asm("cvt.rna.tf32.f32 %0, %1;" : "=r"(u) : "f"(f));
    return u;
}

__device__ __forceinline__ void mma_tf32(float* d, const unsigned* a, const unsigned* b) {
    asm volatile(
        "mma.sync.aligned.m16n8k8.row.col.f32.tf32.tf32.f32 "
        "{%0,%1,%2,%3}, {%4,%5,%6,%7}, {%8,%9}, {%0,%1,%2,%3};"
        : "+f"(d[0]), "+f"(d[1]), "+f"(d[2]), "+f"(d[3])
        : "r"(a[0]), "r"(a[1]), "r"(a[2]), "r"(a[3]),
          "r"(b[0]), "r"(b[1]));
}

template<int ACT>
__global__ __launch_bounds__(256, 1) void tgemm_kernel(
    const float* __restrict__ A, const float* __restrict__ B,
    const float* __restrict__ bias, float* __restrict__ C,
    int M, int N, int K)
{
    __shared__ unsigned As[2][4096];   // 2 x 16KB
    __shared__ unsigned Bs[2][2048];   // 2 x 8KB

    int tid = threadIdx.x;
    int lane = tid & 31, wid = tid >> 5;
    int bm = blockIdx.y * 256, bn = blockIdx.x * 128;

    // ---- staging ----
    const float* Ap = A + (size_t)(bm + tid) * K;       // one A row per thread
    int b_k = tid & 15, b_n = (tid >> 4) * 8;           // B: k-row per thread, 8 n-cols
    const float* Bp = B + (size_t)b_k * N + bn + b_n;

    int abase = ((tid >> 4) << 7) + ((tid >> 3) & 1);   // mblk*128 + m-reg-bit
    int pa[4];
#pragma unroll
    for (int q = 0; q < 4; q++) {
        int la = ((tid & 7) << 2) | q;
        pa[q] = PERM5(la) << 2;
    }
    int bbase = ((b_k >> 3) << 10) + ((b_n >> 3) << 6) + ((b_k >> 2) & 1);
    int pb[8];
#pragma unroll
    for (int j = 0; j < 8; j++) {
        int lb = (j << 2) | (b_k & 3);
        pb[j] = (PERM5(lb) ^ ((b_k >> 3) * 6)) << 1;
    }

    // ---- fragment addressing ----
    int permL = PERM5(lane);
    int afrag = ((wid & 3) << 9) + (permL << 2);        // + g*2048 + mi*128
    int bfrag0 = ((wid >> 2) << 9) + (permL << 1);      // g=0: + ni*64
    int bfrag1 = ((wid >> 2) << 9) + ((permL ^ 6) << 1) + 2048; // g=1 (word 1024*... in B words: +1024)
    bfrag1 = ((wid >> 2) << 9) + ((permL ^ 6) << 1) + 1024;

    float acc[4][8][4];
#pragma unroll
    for (int i = 0; i < 4; i++)
#pragma unroll
        for (int j = 0; j < 8; j++)
#pragma unroll
            for (int l = 0; l < 4; l++) acc[i][j][l] = 0.f;

    float a_f[16], b_f[8];
    {
        float4 t0 = ((const float4*)Ap)[0];
        float4 t1 = ((const float4*)Ap)[1];
        float4 t2 = ((const float4*)Ap)[2];
        float4 t3 = ((const float4*)Ap)[3];
        *(float4*)&a_f[0]  = t0; *(float4*)&a_f[4]  = t1;
        *(float4*)&a_f[8]  = t2; *(float4*)&a_f[12] = t3;
        float4 u0 = ((const float4*)Bp)[0];
        float4 u1 = ((const float4*)Bp)[1];
        *(float4*)&b_f[0] = u0; *(float4*)&b_f[4] = u1;
    }
    // stage tile 0 into buffer 0
    {
        unsigned* Ab = As[0]; unsigned* Bb = Bs[0];
#pragma unroll
        for (int j = 0; j < 16; j++)
            Ab[abase + ((j >> 3) << 11) + pa[j & 3] + (((j >> 2) & 1) << 1)] = f2tf32(a_f[j]);
#pragma unroll
        for (int j = 0; j < 8; j++)
            Bb[bbase + pb[j]] = f2tf32(b_f[j]);
    }
    __syncthreads();

    int nk = K >> 4;
    for (int kt = 0; kt < nk; kt++) {
        int cur = kt & 1;
        if (kt + 1 < nk) {
            Ap += 16;
            Bp += (size_t)16 * N;
            float4 t0 = ((const float4*)Ap)[0];
            float4 t1 = ((const float4*)Ap)[1];
            float4 t2 = ((const float4*)Ap)[2];
            float4 t3 = ((const float4*)Ap)[3];
            *(float4*)&a_f[0]  = t0; *(float4*)&a_f[4]  = t1;
            *(float4*)&a_f[8]  = t2; *(float4*)&a_f[12] = t3;
            float4 u0 = ((const float4*)Bp)[0];
            float4 u1 = ((const float4*)Bp)[1];
            *(float4*)&b_f[0] = u0; *(float4*)&b_f[4] = u1;
        }

        const unsigned* Ab = As[cur];
        const unsigned* Bb = Bs[cur];
#pragma unroll
        for (int g = 0; g < 2; g++) {
            unsigned afr[4][4], bfr[8][2];
#pragma unroll
            for (int mi = 0; mi < 4; mi++) {
                uint4 t = *(const uint4*)&Ab[(g << 11) + afrag + (mi << 7)];
                afr[mi][0] = t.x; afr[mi][1] = t.y; afr[mi][2] = t.z; afr[mi][3] = t.w;
            }
#pragma unroll
            for (int ni = 0; ni < 8; ni++) {
                uint2 u = *(const uint2*)&Bb[(g ? bfrag1 : bfrag0) + (ni << 6)];
                bfr[ni][0] = u.x; bfr[ni][1] = u.y;
            }
#pragma unroll
            for (int mi = 0; mi < 4; mi++)
#pragma unroll
                for (int ni = 0; ni < 8; ni++)
                    mma_tf32(acc[mi][ni], afr[mi], bfr[ni]);
        }

        if (kt + 1 < nk) {
            unsigned* An = As[cur ^ 1]; unsigned* Bn = Bs[cur ^ 1];
#pragma unroll
            for (int j = 0; j < 16; j++)
                An[abase + ((j >> 3) << 11) + pa[j & 3] + (((j >> 2) & 1) << 1)] = f2tf32(a_f[j]);
#pragma unroll
            for (int j = 0; j < 8; j++)
                Bn[bbase + pb[j]] = f2tf32(b_f[j]);
        }
        __syncthreads();
    }

    // ---- epilogue ----
    int lk = lane & 3, lm = lane >> 2;
#pragma unroll
    for (int mi = 0; mi < 4; mi++) {
#pragma unroll
        for (int part = 0; part < 2; part++) {
            int row = bm + (wid & 3) * 64 + mi * 16 + lm + part * 8;
            float* Crow = C + (size_t)row * N;
#pragma unroll
            for (int ni = 0; ni < 8; ni++) {
                int col = bn + (wid >> 2) * 64 + ni * 8 + lk * 2;
                float v0 = acc[mi][ni][part * 2 + 0] + bias[col];
                float v1 = acc[mi][ni][part * 2 + 1] + bias[col + 1];
                if (ACT == 1) {
                    float i0 = fmaf(0.044715f * v0 * v0, v0, v0);
                    v0 = 0.5f * v0 * (1.f + tanhf(0.7978845608028654f * i0));
                    float i1 = fmaf(0.044715f * v1 * v1, v1, v1);
                    v1 = 0.5f * v1 * (1.f + tanhf(0.7978845608028654f * i1));
                }
                *(float2*)(Crow + col) = make_float2(v0, v1);
            }
        }
    }
}

// ---------------- residual + LayerNorm (warp per row) ----------------
__global__ __launch_bounds__(256) void add_ln_kernel(
    const float* __restrict__ res, const float* __restrict__ y,
    const float* __restrict__ sc, const float* __restrict__ bi,
    float* __restrict__ out)
{
    int row  = blockIdx.x * 8 + (threadIdx.x >> 5);
    int lane = threadIdx.x & 31;
    const float* yr = y + (size_t)row * DIMC;
    float v[12];
    float s = 0.f, s2 = 0.f;
    #pragma unroll
    for (int k = 0; k < 12; k++) {
        v[k] = yr[lane + k * 32];
        s += v[k];
        s2 = fmaf(v[k], v[k], s2);
    }
    #pragma unroll
    for (int o = 16; o > 0; o >>= 1) {
        s  += __shfl_xor_sync(0xffffffffu, s,  o);
        s2 += __shfl_xor_sync(0xffffffffu, s2, o);
    }
    float mu  = s * (1.f / 384.f);
    float var = s2 * (1.f / 384.f) - mu * mu;
    float inv = rsqrtf(var + 1e-6f);
    const float* rr = res + (size_t)row * DIMC;
    float* orow = out + (size_t)row * DIMC;
    #pragma unroll
    for (int k = 0; k < 12; k++) {
        int col = lane + k * 32;
        orow[col] = rr[col] + (v[k] - mu) * inv * sc[col] + bi[col];
    }
}

// ---------------- launch ----------------
extern "C" void kernel_launch(void* const* d_in, const int* in_sizes, int n_in,
                              void* d_out, int out_size)
{
    (void)in_sizes; (void)n_in; (void)out_size;
    const float* x        = (const float*)d_in[0];
    const float* qkv_w    = (const float*)d_in[1];
    const float* q_bias   = (const float*)d_in[2];
    const float* v_bias   = (const float*)d_in[3];
    const float* lscale   = (const float*)d_in[4];
    const float* cpb_w1   = (const float*)d_in[5];
    const float* cpb_b1   = (const float*)d_in[6];
    const float* cpb_w2   = (const float*)d_in[7];
    const float* proj_w   = (const float*)d_in[8];
    const float* proj_b   = (const float*)d_in[9];
    const float* n1s      = (const float*)d_in[10];
    const float* n1b      = (const float*)d_in[11];
    const float* fc1_w    = (const float*)d_in[12];
    const float* fc1_b    = (const float*)d_in[13];
    const float* fc2_w    = (const float*)d_in[14];
    const float* fc2_b    = (const float*)d_in[15];
    const float* n2s      = (const float*)d_in[16];
    const float* n2b      = (const float*)d_in[17];
    float* out = (float*)d_out;

    float *qkv, *attn, *tmp, *x1, *hid, *qbias;
    cudaGetSymbolAddress((void**)&qkv,   g_qkv);
    cudaGetSymbolAddress((void**)&attn,  g_attn);
    cudaGetSymbolAddress((void**)&tmp,   g_tmp);
    cudaGetSymbolAddress((void**)&x1,    g_x1);
    cudaGetSymbolAddress((void**)&hid,   g_hid);
    cudaGetSymbolAddress((void**)&qbias, g_qkvbias);

    prep_kernel<<<1, 256>>>(lscale, cpb_w1, cpb_b1, cpb_w2, q_bias, v_bias);

    // qkv = x @ qkv_w + [q_bias, 0, v_bias]
    {
        dim3 grid(QKVC / 128, TROWS / 256);
        tgemm_kernel<0><<<grid, 256>>>(x, qkv_w, qbias, qkv, TROWS, QKVC, DIMC);
    }

    // windowed cosine attention (shift folded into gather/scatter)
    attn_kernel<<<NWIN * NHEAD, 64>>>(qkv, attn);

    // proj
    {
        dim3 grid(DIMC / 128, TROWS / 256);
        tgemm_kernel<0><<<grid, 256>>>(attn, proj_w, proj_b, tmp, TROWS, DIMC, DIMC);
    }

    // x1 = x + LN(proj_out)
    add_ln_kernel<<<TROWS / 8, 256>>>(x, tmp, n1s, n1b, x1);

    // hid = gelu(x1 @ fc1_w + fc1_b)
    {
        dim3 grid(HIDC / 128, TROWS / 256);
        tgemm_kernel<1><<<grid, 256>>>(x1, fc1_w, fc1_b, hid, TROWS, HIDC, DIMC);
    }

    // y = hid @ fc2_w + fc2_b
    {
        dim3 grid(DIMC / 128, TROWS / 256);
        tgemm_kernel<0><<<grid, 256>>>(hid, fc2_w, fc2_b, tmp, TROWS, DIMC, HIDC);
    }

    // out = x1 + LN(y)
    add_ln_kernel<<<TROWS / 8, 256>>>(x1, tmp, n2s, n2b, out);
}

// round 9
// speedup vs baseline: 1.0174x; 1.0174x over previous
#include <cuda_runtime.h>
#include <math.h>

// ---------------- problem constants ----------------
#define TROWS 131072          // B * H * W = 32 * 4096
#define DIMC  384
#define HIDC  1536
#define QKVC  1152
#define NHEAD 12
#define HDIM  32
#define NTOK  64              // tokens per window
#define NWIN  2048            // 32 * 64 windows

// ---------------- scratch (device globals; no allocation) ----------------
__device__ float g_qkv[150994944];   // TROWS * 1152
__device__ float g_attn[50331648];   // TROWS * 384
__device__ float g_tmp[50331648];    // TROWS * 384
__device__ float g_x1[50331648];     // TROWS * 384
__device__ float g_hid[201326592];   // TROWS * 1536
__device__ float g_bias16[NHEAD * 225];
__device__ float g_scale[NHEAD];
__device__ float g_qkvbias[QKVC];

// ---------------- prep: CPB table, head scales, qkv bias ----------------
__device__ __forceinline__ float cpb_norm(int c) {
    float t = (float)c * (8.0f / 7.0f);
    float s = (t > 0.f) ? 1.f : ((t < 0.f) ? -1.f : 0.f);
    return s * log2f(fabsf(t) + 1.0f) * (1.0f / 3.0f);
}

__global__ void prep_kernel(const float* __restrict__ ls,
                            const float* __restrict__ w1,
                            const float* __restrict__ b1,
                            const float* __restrict__ w2,
                            const float* __restrict__ qb,
                            const float* __restrict__ vb)
{
    int tid = threadIdx.x;
    for (int i = tid; i < QKVC; i += 256) {
        float v = 0.f;
        if (i < 384) v = qb[i];
        else if (i >= 768) v = vb[i - 768];
        g_qkvbias[i] = v;
    }
    if (tid < NHEAD) g_scale[tid] = expf(fminf(ls[tid], 4.6051701859880914f)); // ln(100)
    if (tid < 225) {
        int i = tid / 15, j = tid % 15;
        float f0 = cpb_norm(j - 7);
        float f1 = cpb_norm(i - 7);
        float acc[NHEAD];
        #pragma unroll
        for (int h = 0; h < NHEAD; h++) acc[h] = 0.f;
        for (int u = 0; u < 512; u++) {
            float hu = fmaf(f0, w1[u], fmaf(f1, w1[512 + u], b1[u]));
            hu = fmaxf(hu, 0.f);
            #pragma unroll
            for (int h = 0; h < NHEAD; h++) acc[h] = fmaf(hu, w2[u * 12 + h], acc[h]);
        }
        #pragma unroll
        for (int h = 0; h < NHEAD; h++)
            g_bias16[h * 225 + tid] = 16.f / (1.f + expf(-acc[h]));
    }
}

// ---------------- attention: one (window, head) per block ----------------
__global__ __launch_bounds__(64) void attn_kernel(const float* __restrict__ qkv,
                                                  float* __restrict__ out)
{
    __shared__ float kn[64][33];
    __shared__ float vs[64][33];
    __shared__ float bia[225];
    __shared__ int   lab[64];

    int blk  = blockIdx.x;
    int head = blk % NHEAD;
    int w    = blk / NHEAD;
    int b    = w >> 6;
    int win  = w & 63;
    int wh = win >> 3, ww = win & 7;
    int t = threadIdx.x;
    int r = t >> 3, c = t & 7;
    int hp = wh * 8 + r, wp = ww * 8 + c;
    int sh = (hp + 4) & 63, sw = (wp + 4) & 63;
    size_t row = (size_t)b * 4096 + (size_t)sh * 64 + sw;
    const float* base = qkv + row * QKVC + head * HDIM;

    int lh = (hp < 56) ? 0 : ((hp < 60) ? 1 : 2);
    int lw = (wp < 56) ? 0 : ((wp < 60) ? 1 : 2);
    lab[t] = lh * 3 + lw;

    for (int i = t; i < 225; i += 64) bia[i] = g_bias16[head * 225 + i];

    float qreg[HDIM];
    {
        float tmp[HDIM];
        float nk = 0.f;
        #pragma unroll
        for (int d4 = 0; d4 < 8; d4++) {
            float4 v4 = *(const float4*)(base + 384 + d4 * 4);
            tmp[d4*4+0] = v4.x; tmp[d4*4+1] = v4.y; tmp[d4*4+2] = v4.z; tmp[d4*4+3] = v4.w;
        }
        #pragma unroll
        for (int d = 0; d < HDIM; d++) nk = fmaf(tmp[d], tmp[d], nk);
        float invk = 1.0f / sqrtf(nk);
        #pragma unroll
        for (int d = 0; d < HDIM; d++) kn[t][d] = tmp[d] * invk;

        #pragma unroll
        for (int d4 = 0; d4 < 8; d4++) {
            float4 v4 = *(const float4*)(base + 768 + d4 * 4);
            vs[t][d4*4+0] = v4.x; vs[t][d4*4+1] = v4.y; vs[t][d4*4+2] = v4.z; vs[t][d4*4+3] = v4.w;
        }

        float nq = 0.f;
        #pragma unroll
        for (int d4 = 0; d4 < 8; d4++) {
            float4 v4 = *(const float4*)(base + d4 * 4);
            qreg[d4*4+0] = v4.x; qreg[d4*4+1] = v4.y; qreg[d4*4+2] = v4.z; qreg[d4*4+3] = v4.w;
        }
        #pragma unroll
        for (int d = 0; d < HDIM; d++) nq = fmaf(qreg[d], qreg[d], nq);
        float invq = g_scale[head] / sqrtf(nq);
        #pragma unroll
        for (int d = 0; d < HDIM; d++) qreg[d] *= invq;
    }
    __syncthreads();

    float lg[NTOK];
    float mx = -1e30f;
    int myl = lab[t];
    for (int t2 = 0; t2 < NTOK; t2++) {
        float acc = 0.f;
        #pragma unroll
        for (int d = 0; d < HDIM; d++) acc = fmaf(qreg[d], kn[t2][d], acc);
        int r2 = t2 >> 3, c2 = t2 & 7;
        acc += bia[(c - c2 + 7) * 15 + (r - r2 + 7)];
        if (myl != lab[t2]) acc -= 100.f;
        lg[t2] = acc;
        mx = fmaxf(mx, acc);
    }
    float ssum = 0.f;
    for (int t2 = 0; t2 < NTOK; t2++) {
        lg[t2] = __expf(lg[t2] - mx);
        ssum += lg[t2];
    }
    float isum = 1.0f / ssum;
    for (int t2 = 0; t2 < NTOK; t2++) lg[t2] *= isum;

    float* orow = out + row * DIMC + head * HDIM;
    for (int d = 0; d < HDIM; d++) {
        float acc = 0.f;
        for (int t2 = 0; t2 < NTOK; t2++) acc = fmaf(lg[t2], vs[t2][d], acc);
        orow[d] = acc;
    }
}

// ---------------- tf32 tensor-core GEMM, 128x128 CTA, 8 warps of 64x32 ----------------
// Fragment-ready smem layouts (vectorized fragment loads):
//  A: element (m,k), m in [0,128), k in [0,16):
//     word = (k>>3)*1024 + (m>>4)*128 + PERM5((m&7)*4 + (k&3))*4
//            + ((k>>2)&1)*2 + ((m>>3)&1)
//     -> warp A-fragment (m16 x k8) = one LDS.128 at base + PERM5(lane)*4
//  B: element (k,n), k in [0,16), n in [0,128):
//     word = (k>>3)*1024 + (n>>3)*64 + (PERM5((n&7)*4 + (k&3)) ^ ((k>>3)*6))*2
//            + ((k>>2)&1)
//     -> warp B-fragment (k8 x n8) = one LDS.64
#define PERM5(x) ((x) ^ ((x) >> 2))

__device__ __forceinline__ unsigned f2tf32(float f) {
    unsigned u;
    asm("cvt.rna.tf32.f32 %0, %1;" : "=r"(u) : "f"(f));
    return u;
}

__device__ __forceinline__ void mma_tf32(float* d, const unsigned* a, const unsigned* b) {
    asm volatile(
        "mma.sync.aligned.m16n8k8.row.col.f32.tf32.tf32.f32 "
        "{%0,%1,%2,%3}, {%4,%5,%6,%7}, {%8,%9}, {%0,%1,%2,%3};"
        : "+f"(d[0]), "+f"(d[1]), "+f"(d[2]), "+f"(d[3])
        : "r"(a[0]), "r"(a[1]), "r"(a[2]), "r"(a[3]),
          "r"(b[0]), "r"(b[1]));
}

template<int ACT>
__global__ __launch_bounds__(256, 2) void tgemm_kernel(
    const float* __restrict__ A, const float* __restrict__ B,
    const float* __restrict__ bias, float* __restrict__ C,
    int M, int N, int K)
{
    __shared__ unsigned As[2][2048];   // 2 x 8KB
    __shared__ unsigned Bs[2][2048];   // 2 x 8KB

    int tid = threadIdx.x;
    int lane = tid & 31, wid = tid >> 5;
    int wm = (wid & 1) * 64;           // warp m-offset
    int wn = (wid >> 1) * 32;          // warp n-offset
    int bm = blockIdx.y * 128, bn = blockIdx.x * 128;

    // ---- staging addresses ----
    int a_r = tid >> 1, a_k = (tid & 1) * 8;            // A: row, k-base (2 float4)
    const float* Ap = A + (size_t)(bm + a_r) * K + a_k;
    int b_k = tid & 15, b_n = (tid >> 4) * 8;           // B: k-row, 8 n-cols
    const float* Bp = B + (size_t)b_k * N + bn + b_n;

    int abase = ((a_k >> 3) << 10) + ((a_r >> 4) << 7) + ((a_r >> 3) & 1);
    int pa[4];
#pragma unroll
    for (int q = 0; q < 4; q++)
        pa[q] = PERM5(((a_r & 7) << 2) | q) << 2;

    int bbase = ((b_k >> 3) << 10) + ((b_n >> 3) << 6) + ((b_k >> 2) & 1);
    int pb[8];
#pragma unroll
    for (int j = 0; j < 8; j++)
        pb[j] = (PERM5((j << 2) | (b_k & 3)) ^ ((b_k >> 3) * 6)) << 1;

    // ---- fragment addresses ----
    int permL = PERM5(lane);
    int afrag = ((wid & 1) << 9) + (permL << 2);        // + g*1024 + mi*128
    int bfrag0 = ((wid >> 1) << 8) + (permL << 1);              // g=0, + ni*64
    int bfrag1 = 1024 + ((wid >> 1) << 8) + ((permL ^ 6) << 1); // g=1, + ni*64

    float acc[4][4][4];
#pragma unroll
    for (int i = 0; i < 4; i++)
#pragma unroll
        for (int j = 0; j < 4; j++)
#pragma unroll
            for (int l = 0; l < 4; l++) acc[i][j][l] = 0.f;

    float a_f[8], b_f[8];
    {
        float4 t0 = ((const float4*)Ap)[0];
        float4 t1 = ((const float4*)Ap)[1];
        *(float4*)&a_f[0] = t0; *(float4*)&a_f[4] = t1;
        float4 u0 = ((const float4*)Bp)[0];
        float4 u1 = ((const float4*)Bp)[1];
        *(float4*)&b_f[0] = u0; *(float4*)&b_f[4] = u1;
    }
    {
        unsigned* Ab = As[0]; unsigned* Bb = Bs[0];
#pragma unroll
        for (int j = 0; j < 8; j++)
            Ab[abase + pa[j & 3] + (((j >> 2) & 1) << 1)] = f2tf32(a_f[j]);
#pragma unroll
        for (int j = 0; j < 8; j++)
            Bb[bbase + pb[j]] = f2tf32(b_f[j]);
    }
    __syncthreads();

    int nk = K >> 4;
    for (int kt = 0; kt < nk; kt++) {
        int cur = kt & 1;
        if (kt + 1 < nk) {
            Ap += 16;
            Bp += (size_t)16 * N;
            float4 t0 = ((const float4*)Ap)[0];
            float4 t1 = ((const float4*)Ap)[1];
            *(float4*)&a_f[0] = t0; *(float4*)&a_f[4] = t1;
            float4 u0 = ((const float4*)Bp)[0];
            float4 u1 = ((const float4*)Bp)[1];
            *(float4*)&b_f[0] = u0; *(float4*)&b_f[4] = u1;
        }

        const unsigned* Ab = As[cur];
        const unsigned* Bb = Bs[cur];
#pragma unroll
        for (int g = 0; g < 2; g++) {
            unsigned afr[4][4], bfr[4][2];
#pragma unroll
            for (int mi = 0; mi < 4; mi++) {
                uint4 t = *(const uint4*)&Ab[(g << 10) + afrag + (mi << 7)];
                afr[mi][0] = t.x; afr[mi][1] = t.y; afr[mi][2] = t.z; afr[mi][3] = t.w;
            }
#pragma unroll
            for (int ni = 0; ni < 4; ni++) {
                uint2 u = *(const uint2*)&Bb[(g ? bfrag1 : bfrag0) + (ni << 6)];
                bfr[ni][0] = u.x; bfr[ni][1] = u.y;
            }
#pragma unroll
            for (int mi = 0; mi < 4; mi++)
#pragma unroll
                for (int ni = 0; ni < 4; ni++)
                    mma_tf32(acc[mi][ni], afr[mi], bfr[ni]);
        }

        if (kt + 1 < nk) {
            unsigned* An = As[cur ^ 1]; unsigned* Bn = Bs[cur ^ 1];
#pragma unroll
            for (int j = 0; j < 8; j++)
                An[abase + pa[j & 3] + (((j >> 2) & 1) << 1)] = f2tf32(a_f[j]);
#pragma unroll
            for (int j = 0; j < 8; j++)
                Bn[bbase + pb[j]] = f2tf32(b_f[j]);
        }
        __syncthreads();
    }

    // ---- epilogue ----
    int lk = lane & 3, lm = lane >> 2;
#pragma unroll
    for (int mi = 0; mi < 4; mi++) {
#pragma unroll
        for (int part = 0; part < 2; part++) {
            int row = bm + wm + mi * 16 + lm + part * 8;
            float* Crow = C + (size_t)row * N;
#pragma unroll
            for (int ni = 0; ni < 4; ni++) {
                int col = bn + wn + ni * 8 + lk * 2;
                float v0 = acc[mi][ni][part * 2 + 0] + bias[col];
                float v1 = acc[mi][ni][part * 2 + 1] + bias[col + 1];
                if (ACT == 1) {
                    float i0 = fmaf(0.044715f * v0 * v0, v0, v0);
                    v0 = 0.5f * v0 * (1.f + tanhf(0.7978845608028654f * i0));
                    float i1 = fmaf(0.044715f * v1 * v1, v1, v1);
                    v1 = 0.5f * v1 * (1.f + tanhf(0.7978845608028654f * i1));
                }
                *(float2*)(Crow + col) = make_float2(v0, v1);
            }
        }
    }
}

// ---------------- residual + LayerNorm (warp per row) ----------------
__global__ __launch_bounds__(256) void add_ln_kernel(
    const float* __restrict__ res, const float* __restrict__ y,
    const float* __restrict__ sc, const float* __restrict__ bi,
    float* __restrict__ out)
{
    int row  = blockIdx.x * 8 + (threadIdx.x >> 5);
    int lane = threadIdx.x & 31;
    const float* yr = y + (size_t)row * DIMC;
    float v[12];
    float s = 0.f, s2 = 0.f;
    #pragma unroll
    for (int k = 0; k < 12; k++) {
        v[k] = yr[lane + k * 32];
        s += v[k];
        s2 = fmaf(v[k], v[k], s2);
    }
    #pragma unroll
    for (int o = 16; o > 0; o >>= 1) {
        s  += __shfl_xor_sync(0xffffffffu, s,  o);
        s2 += __shfl_xor_sync(0xffffffffu, s2, o);
    }
    float mu  = s * (1.f / 384.f);
    float var = s2 * (1.f / 384.f) - mu * mu;
    float inv = rsqrtf(var + 1e-6f);
    const float* rr = res + (size_t)row * DIMC;
    float* orow = out + (size_t)row * DIMC;
    #pragma unroll
    for (int k = 0; k < 12; k++) {
        int col = lane + k * 32;
        orow[col] = rr[col] + (v[k] - mu) * inv * sc[col] + bi[col];
    }
}

// ---------------- launch ----------------
extern "C" void kernel_launch(void* const* d_in, const int* in_sizes, int n_in,
                              void* d_out, int out_size)
{
    (void)in_sizes; (void)n_in; (void)out_size;
    const float* x        = (const float*)d_in[0];
    const float* qkv_w    = (const float*)d_in[1];
    const float* q_bias   = (const float*)d_in[2];
    const float* v_bias   = (const float*)d_in[3];
    const float* lscale   = (const float*)d_in[4];
    const float* cpb_w1   = (const float*)d_in[5];
    const float* cpb_b1   = (const float*)d_in[6];
    const float* cpb_w2   = (const float*)d_in[7];
    const float* proj_w   = (const float*)d_in[8];
    const float* proj_b   = (const float*)d_in[9];
    const float* n1s      = (const float*)d_in[10];
    const float* n1b      = (const float*)d_in[11];
    const float* fc1_w    = (const float*)d_in[12];
    const float* fc1_b    = (const float*)d_in[13];
    const float* fc2_w    = (const float*)d_in[14];
    const float* fc2_b    = (const float*)d_in[15];
    const float* n2s      = (const float*)d_in[16];
    const float* n2b      = (const float*)d_in[17];
    float* out = (float*)d_out;

    float *qkv, *attn, *tmp, *x1, *hid, *qbias;
    cudaGetSymbolAddress((void**)&qkv,   g_qkv);
    cudaGetSymbolAddress((void**)&attn,  g_attn);
    cudaGetSymbolAddress((void**)&tmp,   g_tmp);
    cudaGetSymbolAddress((void**)&x1,    g_x1);
    cudaGetSymbolAddress((void**)&hid,   g_hid);
    cudaGetSymbolAddress((void**)&qbias, g_qkvbias);

    prep_kernel<<<1, 256>>>(lscale, cpb_w1, cpb_b1, cpb_w2, q_bias, v_bias);

    // qkv = x @ qkv_w + [q_bias, 0, v_bias]
    {
        dim3 grid(QKVC / 128, TROWS / 128);
        tgemm_kernel<0><<<grid, 256>>>(x, qkv_w, qbias, qkv, TROWS, QKVC, DIMC);
    }

    // windowed cosine attention (shift folded into gather/scatter)
    attn_kernel<<<NWIN * NHEAD, 64>>>(qkv, attn);

    // proj
    {
        dim3 grid(DIMC / 128, TROWS / 128);
        tgemm_kernel<0><<<grid, 256>>>(attn, proj_w, proj_b, tmp, TROWS, DIMC, DIMC);
    }

    // x1 = x + LN(proj_out)
    add_ln_kernel<<<TROWS / 8, 256>>>(x, tmp, n1s, n1b, x1);

    // hid = gelu(x1 @ fc1_w + fc1_b)
    {
        dim3 grid(HIDC / 128, TROWS / 128);
        tgemm_kernel<1><<<grid, 256>>>(x1, fc1_w, fc1_b, hid, TROWS, HIDC, DIMC);
    }

    // y = hid @ fc2_w + fc2_b
    {
        dim3 grid(DIMC / 128, TROWS / 128);
        tgemm_kernel<0><<<grid, 256>>>(hid, fc2_w, fc2_b, tmp, TROWS, DIMC, HIDC);
    }

    // out = x1 + LN(y)
    add_ln_kernel<<<TROWS / 8, 256>>>(x1, tmp, n2s, n2b, out);
}

// round 12
// speedup vs baseline: 1.3918x; 1.3679x over previous
#include <cuda_runtime.h>
#include <cuda_fp16.h>
#include <math.h>
#include <stdint.h>

// ---------------- problem constants ----------------
#define TROWS 131072          // B * H * W = 32 * 4096
#define DIMC  384
#define HIDC  1536
#define QKVC  1152
#define NHEAD 12
#define HDIM  32
#define NTOK  64              // tokens per window
#define NWIN  2048            // 32 * 64 windows

// ---------------- scratch (device globals; no allocation) ----------------
__device__ float g_qkv[150994944];   // TROWS * 1152
__device__ float g_attn[50331648];   // TROWS * 384
__device__ float g_tmp[50331648];    // TROWS * 384
__device__ float g_x1[50331648];     // TROWS * 384
__device__ float g_hid[201326592];   // TROWS * 1536
__device__ float g_bias16[NHEAD * 225];
__device__ float g_scale[NHEAD];
__device__ float g_qkvbias[QKVC];

// ---------------- prep: CPB table, head scales, qkv bias ----------------
__device__ __forceinline__ float cpb_norm(int c) {
    float t = (float)c * (8.0f / 7.0f);
    float s = (t > 0.f) ? 1.f : ((t < 0.f) ? -1.f : 0.f);
    return s * log2f(fabsf(t) + 1.0f) * (1.0f / 3.0f);
}

__global__ void prep_kernel(const float* __restrict__ ls,
                            const float* __restrict__ w1,
                            const float* __restrict__ b1,
                            const float* __restrict__ w2,
                            const float* __restrict__ qb,
                            const float* __restrict__ vb)
{
    int tid = threadIdx.x;
    for (int i = tid; i < QKVC; i += 256) {
        float v = 0.f;
        if (i < 384) v = qb[i];
        else if (i >= 768) v = vb[i - 768];
        g_qkvbias[i] = v;
    }
    if (tid < NHEAD) g_scale[tid] = expf(fminf(ls[tid], 4.6051701859880914f)); // ln(100)
    if (tid < 225) {
        int i = tid / 15, j = tid % 15;
        float f0 = cpb_norm(j - 7);
        float f1 = cpb_norm(i - 7);
        float acc[NHEAD];
        #pragma unroll
        for (int h = 0; h < NHEAD; h++) acc[h] = 0.f;
        for (int u = 0; u < 512; u++) {
            float hu = fmaf(f0, w1[u], fmaf(f1, w1[512 + u], b1[u]));
            hu = fmaxf(hu, 0.f);
            #pragma unroll
            for (int h = 0; h < NHEAD; h++) acc[h] = fmaf(hu, w2[u * 12 + h], acc[h]);
        }
        #pragma unroll
        for (int h = 0; h < NHEAD; h++)
            g_bias16[h * 225 + tid] = 16.f / (1.f + expf(-acc[h]));
    }
}

// ---------------- attention: one (window, head) per block ----------------
__global__ __launch_bounds__(64) void attn_kernel(const float* __restrict__ qkv,
                                                  float* __restrict__ out)
{
    __shared__ float kn[64][33];
    __shared__ float vs[64][33];
    __shared__ float bia[225];
    __shared__ int   lab[64];

    int blk  = blockIdx.x;
    int head = blk % NHEAD;
    int w    = blk / NHEAD;
    int b    = w >> 6;
    int win  = w & 63;
    int wh = win >> 3, ww = win & 7;
    int t = threadIdx.x;
    int r = t >> 3, c = t & 7;
    int hp = wh * 8 + r, wp = ww * 8 + c;
    int sh = (hp + 4) & 63, sw = (wp + 4) & 63;
    size_t row = (size_t)b * 4096 + (size_t)sh * 64 + sw;
    const float* base = qkv + row * QKVC + head * HDIM;

    int lh = (hp < 56) ? 0 : ((hp < 60) ? 1 : 2);
    int lw = (wp < 56) ? 0 : ((wp < 60) ? 1 : 2);
    lab[t] = lh * 3 + lw;

    for (int i = t; i < 225; i += 64) bia[i] = g_bias16[head * 225 + i];

    float qreg[HDIM];
    {
        float tmp[HDIM];
        float nk = 0.f;
        #pragma unroll
        for (int d4 = 0; d4 < 8; d4++) {
            float4 v4 = *(const float4*)(base + 384 + d4 * 4);
            tmp[d4*4+0] = v4.x; tmp[d4*4+1] = v4.y; tmp[d4*4+2] = v4.z; tmp[d4*4+3] = v4.w;
        }
        #pragma unroll
        for (int d = 0; d < HDIM; d++) nk = fmaf(tmp[d], tmp[d], nk);
        float invk = 1.0f / sqrtf(nk);
        #pragma unroll
        for (int d = 0; d < HDIM; d++) kn[t][d] = tmp[d] * invk;

        #pragma unroll
        for (int d4 = 0; d4 < 8; d4++) {
            float4 v4 = *(const float4*)(base + 768 + d4 * 4);
            vs[t][d4*4+0] = v4.x; vs[t][d4*4+1] = v4.y; vs[t][d4*4+2] = v4.z; vs[t][d4*4+3] = v4.w;
        }

        float nq = 0.f;
        #pragma unroll
        for (int d4 = 0; d4 < 8; d4++) {
            float4 v4 = *(const float4*)(base + d4 * 4);
            qreg[d4*4+0] = v4.x; qreg[d4*4+1] = v4.y; qreg[d4*4+2] = v4.z; qreg[d4*4+3] = v4.w;
        }
        #pragma unroll
        for (int d = 0; d < HDIM; d++) nq = fmaf(qreg[d], qreg[d], nq);
        float invq = g_scale[head] / sqrtf(nq);
        #pragma unroll
        for (int d = 0; d < HDIM; d++) qreg[d] *= invq;
    }
    __syncthreads();

    float lg[NTOK];
    float mx = -1e30f;
    int myl = lab[t];
    for (int t2 = 0; t2 < NTOK; t2++) {
        float acc = 0.f;
        #pragma unroll
        for (int d = 0; d < HDIM; d++) acc = fmaf(qreg[d], kn[t2][d], acc);
        int r2 = t2 >> 3, c2 = t2 & 7;
        acc += bia[(c - c2 + 7) * 15 + (r - r2 + 7)];
        if (myl != lab[t2]) acc -= 100.f;
        lg[t2] = acc;
        mx = fmaxf(mx, acc);
    }
    float ssum = 0.f;
    for (int t2 = 0; t2 < NTOK; t2++) {
        lg[t2] = __expf(lg[t2] - mx);
        ssum += lg[t2];
    }
    float isum = 1.0f / ssum;
    for (int t2 = 0; t2 < NTOK; t2++) lg[t2] *= isum;

    float* orow = out + row * DIMC + head * HDIM;
    for (int d = 0; d < HDIM; d++) {
        float acc = 0.f;
        for (int t2 = 0; t2 < NTOK; t2++) acc = fmaf(lg[t2], vs[t2][d], acc);
        orow[d] = acc;
    }
}

// ================ fp16 tensor-core GEMM (mma.m16n8k16 + ldmatrix) ================
// C[M,N] = A[M,K] @ B[K,N] + bias (opt GELU). fp16 operands, fp32 accumulate.
// CTA 128x128, BK=32, 8 warps of 64x32, double-buffered smem.
// A smem: [128 m][32 k] halves, row stride 80B  (5 chunks; 5 coprime 8 -> ldmatrix
//         loads conflict-free: group=(5m+c)%8 distinct over any 8 consecutive m)
// B smem: [32 k][128 n] halves, row stride 272B (17 chunks; 17%8=1 -> group=(k+c)%8
//         distinct over 8 consecutive k for fixed n-chunk). Fragments via ldmatrix.trans.

#define ASTRB 80
#define BSTRB 272

__device__ __forceinline__ uint32_t ph2(float lo, float hi) {
    __half2 h = __floats2half2_rn(lo, hi);
    return *(uint32_t*)&h;
}

__device__ __forceinline__ void ldsm_x4(uint32_t* r, uint32_t addr) {
    asm volatile("ldmatrix.sync.aligned.m8n8.x4.shared.b16 {%0,%1,%2,%3}, [%4];"
                 : "=r"(r[0]), "=r"(r[1]), "=r"(r[2]), "=r"(r[3]) : "r"(addr));
}

__device__ __forceinline__ void ldsm_x2t(uint32_t* r, uint32_t addr) {
    asm volatile("ldmatrix.sync.aligned.m8n8.x2.trans.shared.b16 {%0,%1}, [%2];"
                 : "=r"(r[0]), "=r"(r[1]) : "r"(addr));
}

__device__ __forceinline__ void mma_f16(float* d, const uint32_t* a, const uint32_t* b) {
    asm volatile(
        "mma.sync.aligned.m16n8k16.row.col.f32.f16.f16.f32 "
        "{%0,%1,%2,%3}, {%4,%5,%6,%7}, {%8,%9}, {%0,%1,%2,%3};"
        : "+f"(d[0]), "+f"(d[1]), "+f"(d[2]), "+f"(d[3])
        : "r"(a[0]), "r"(a[1]), "r"(a[2]), "r"(a[3]), "r"(b[0]), "r"(b[1]));
}

template<int ACT>
__global__ __launch_bounds__(256, 2) void hgemm_kernel(
    const float* __restrict__ A, const float* __restrict__ B,
    const float* __restrict__ bias, float* __restrict__ C,
    int M, int N, int K)
{
    __shared__ __align__(16) char Asm[2][128 * ASTRB];   // 2 x 10240 B
    __shared__ __align__(16) char Bsm[2][32 * BSTRB];    // 2 x 8704 B

    int tid = threadIdx.x;
    int lane = tid & 31, wid = tid >> 5;
    int wm = (wid & 1) * 64;
    int wn = (wid >> 1) * 32;
    int bm = blockIdx.y * 128, bn = blockIdx.x * 128;

    // ---- staging assignment ----
    int a_r = tid & 127, a_h = tid >> 7;                 // A: row, k-half(16)
    const float* Ap = A + (size_t)(bm + a_r) * K + a_h * 16;
    int b_k = tid >> 4, b_c = tid & 15;                  // B: k-row (and +16), n-chunk(8)
    const float* Bp = B + (size_t)b_k * N + bn + b_c * 8;

    // ---- fragment lane addressing ----
    int rowA = wm + ((lane >> 3) & 1) * 8 + (lane & 7);  // + mi*16
    int colA = lane >> 4;                                // k8-chunk within k16
    int rowB = lane & 15;                                // k within k16 step

    float acc[4][4][4];
#pragma unroll
    for (int i = 0; i < 4; i++)
#pragma unroll
        for (int j = 0; j < 4; j++)
#pragma unroll
            for (int l = 0; l < 4; l++) acc[i][j][l] = 0.f;

    uint32_t ua[8], ub0[4], ub1[4];      // staged halves (packed)

    // load tile kt from gmem, convert to packed halves in regs
    auto ldg_cvt = [&](int kt) {
        const float* ap = Ap + kt * 32;
#pragma unroll
        for (int j = 0; j < 4; j++) {
            float4 v = *(const float4*)(ap + j * 4);
            ua[j*2+0] = ph2(v.x, v.y);
            ua[j*2+1] = ph2(v.z, v.w);
        }
        const float* bp = Bp + (size_t)(kt * 32) * N;
        {
            float4 w0 = ((const float4*)bp)[0];
            float4 w1 = ((const float4*)bp)[1];
            ub0[0] = ph2(w0.x, w0.y); ub0[1] = ph2(w0.z, w0.w);
            ub0[2] = ph2(w1.x, w1.y); ub0[3] = ph2(w1.z, w1.w);
        }
        {
            const float* bp2 = bp + (size_t)16 * N;
            float4 w0 = ((const float4*)bp2)[0];
            float4 w1 = ((const float4*)bp2)[1];
            ub1[0] = ph2(w0.x, w0.y); ub1[1] = ph2(w0.z, w0.w);
            ub1[2] = ph2(w1.x, w1.y); ub1[3] = ph2(w1.z, w1.w);
        }
    };
    auto sts = [&](int bf) {
        char* Ab = Asm[bf]; char* Bb = Bsm[bf];
        *(uint4*)(Ab + a_r * ASTRB + a_h * 32)      = make_uint4(ua[0], ua[1], ua[2], ua[3]);
        *(uint4*)(Ab + a_r * ASTRB + a_h * 32 + 16) = make_uint4(ua[4], ua[5], ua[6], ua[7]);
        *(uint4*)(Bb + b_k * BSTRB + b_c * 16)        = make_uint4(ub0[0], ub0[1], ub0[2], ub0[3]);
        *(uint4*)(Bb + (b_k + 16) * BSTRB + b_c * 16) = make_uint4(ub1[0], ub1[1], ub1[2], ub1[3]);
    };

    ldg_cvt(0);
    sts(0);
    __syncthreads();

    int nk = K >> 5;
    for (int kt = 0; kt < nk; kt++) {
        int cur = kt & 1;
        if (kt + 1 < nk) ldg_cvt(kt + 1);

        uint32_t Abase = (uint32_t)__cvta_generic_to_shared(Asm[cur])
                         + (uint32_t)(rowA * ASTRB + colA * 16);
        uint32_t Bbase = (uint32_t)__cvta_generic_to_shared(Bsm[cur])
                         + (uint32_t)(rowB * BSTRB + wn * 2);
#pragma unroll
        for (int ks = 0; ks < 2; ks++) {
            uint32_t af[4][4], bf[4][2];
#pragma unroll
            for (int mi = 0; mi < 4; mi++)
                ldsm_x4(af[mi], Abase + mi * (16 * ASTRB) + ks * 32);
#pragma unroll
            for (int ni = 0; ni < 4; ni++)
                ldsm_x2t(bf[ni], Bbase + ks * (16 * BSTRB) + ni * 16);
#pragma unroll
            for (int mi = 0; mi < 4; mi++)
#pragma unroll
                for (int ni = 0; ni < 4; ni++)
                    mma_f16(acc[mi][ni], af[mi], bf[ni]);
        }

        if (kt + 1 < nk) sts(cur ^ 1);
        __syncthreads();
    }

    // ---- epilogue (D frag: lane l -> rows l/4, l/4+8; cols (l%4)*2,+1) ----
    int lk = lane & 3, lm = lane >> 2;
#pragma unroll
    for (int mi = 0; mi < 4; mi++) {
#pragma unroll
        for (int part = 0; part < 2; part++) {
            int row = bm + wm + mi * 16 + lm + part * 8;
            float* Crow = C + (size_t)row * N;
#pragma unroll
            for (int ni = 0; ni < 4; ni++) {
                int col = bn + wn + ni * 8 + lk * 2;
                float v0 = acc[mi][ni][part * 2 + 0] + bias[col];
                float v1 = acc[mi][ni][part * 2 + 1] + bias[col + 1];
                if (ACT == 1) {
                    float i0 = fmaf(0.044715f * v0 * v0, v0, v0);
                    v0 = 0.5f * v0 * (1.f + tanhf(0.7978845608028654f * i0));
                    float i1 = fmaf(0.044715f * v1 * v1, v1, v1);
                    v1 = 0.5f * v1 * (1.f + tanhf(0.7978845608028654f * i1));
                }
                *(float2*)(Crow + col) = make_float2(v0, v1);
            }
        }
    }
}

// ---------------- residual + LayerNorm (warp per row) ----------------
__global__ __launch_bounds__(256) void add_ln_kernel(
    const float* __restrict__ res, const float* __restrict__ y,
    const float* __restrict__ sc, const float* __restrict__ bi,
    float* __restrict__ out)
{
    int row  = blockIdx.x * 8 + (threadIdx.x >> 5);
    int lane = threadIdx.x & 31;
    const float* yr = y + (size_t)row * DIMC;
    float v[12];
    float s = 0.f, s2 = 0.f;
    #pragma unroll
    for (int k = 0; k < 12; k++) {
        v[k] = yr[lane + k * 32];
        s += v[k];
        s2 = fmaf(v[k], v[k], s2);
    }
    #pragma unroll
    for (int o = 16; o > 0; o >>= 1) {
        s  += __shfl_xor_sync(0xffffffffu, s,  o);
        s2 += __shfl_xor_sync(0xffffffffu, s2, o);
    }
    float mu  = s * (1.f / 384.f);
    float var = s2 * (1.f / 384.f) - mu * mu;
    float inv = rsqrtf(var + 1e-6f);
    const float* rr = res + (size_t)row * DIMC;
    float* orow = out + (size_t)row * DIMC;
    #pragma unroll
    for (int k = 0; k < 12; k++) {
        int col = lane + k * 32;
        orow[col] = rr[col] + (v[k] - mu) * inv * sc[col] + bi[col];
    }
}

// ---------------- launch ----------------
extern "C" void kernel_launch(void* const* d_in, const int* in_sizes, int n_in,
                              void* d_out, int out_size)
{
    (void)in_sizes; (void)n_in; (void)out_size;
    const float* x        = (const float*)d_in[0];
    const float* qkv_w    = (const float*)d_in[1];
    const float* q_bias   = (const float*)d_in[2];
    const float* v_bias   = (const float*)d_in[3];
    const float* lscale   = (const float*)d_in[4];
    const float* cpb_w1   = (const float*)d_in[5];
    const float* cpb_b1   = (const float*)d_in[6];
    const float* cpb_w2   = (const float*)d_in[7];
    const float* proj_w   = (const float*)d_in[8];
    const float* proj_b   = (const float*)d_in[9];
    const float* n1s      = (const float*)d_in[10];
    const float* n1b      = (const float*)d_in[11];
    const float* fc1_w    = (const float*)d_in[12];
    const float* fc1_b    = (const float*)d_in[13];
    const float* fc2_w    = (const float*)d_in[14];
    const float* fc2_b    = (const float*)d_in[15];
    const float* n2s      = (const float*)d_in[16];
    const float* n2b      = (const float*)d_in[17];
    float* out = (float*)d_out;

    float *qkv, *attn, *tmp, *x1, *hid, *qbias;
    cudaGetSymbolAddress((void**)&qkv,   g_qkv);
    cudaGetSymbolAddress((void**)&attn,  g_attn);
    cudaGetSymbolAddress((void**)&tmp,   g_tmp);
    cudaGetSymbolAddress((void**)&x1,    g_x1);
    cudaGetSymbolAddress((void**)&hid,   g_hid);
    cudaGetSymbolAddress((void**)&qbias, g_qkvbias);

    prep_kernel<<<1, 256>>>(lscale, cpb_w1, cpb_b1, cpb_w2, q_bias, v_bias);

    // qkv = x @ qkv_w + [q_bias, 0, v_bias]
    {
        dim3 grid(QKVC / 128, TROWS / 128);
        hgemm_kernel<0><<<grid, 256>>>(x, qkv_w, qbias, qkv, TROWS, QKVC, DIMC);
    }

    // windowed cosine attention (shift folded into gather/scatter)
    attn_kernel<<<NWIN * NHEAD, 64>>>(qkv, attn);

    // proj
    {
        dim3 grid(DIMC / 128, TROWS / 128);
        hgemm_kernel<0><<<grid, 256>>>(attn, proj_w, proj_b, tmp, TROWS, DIMC, DIMC);
    }

    // x1 = x + LN(proj_out)
    add_ln_kernel<<<TROWS / 8, 256>>>(x, tmp, n1s, n1b, x1);

    // hid = gelu(x1 @ fc1_w + fc1_b)
    {
        dim3 grid(HIDC / 128, TROWS / 128);
        hgemm_kernel<1><<<grid, 256>>>(x1, fc1_w, fc1_b, hid, TROWS, HIDC, DIMC);
    }

    // y = hid @ fc2_w + fc2_b
    {
        dim3 grid(DIMC / 128, TROWS / 128);
        hgemm_kernel<0><<<grid, 256>>>(hid, fc2_w, fc2_b, tmp, TROWS, DIMC, HIDC);
    }

    // out = x1 + LN(y)
    add_ln_kernel<<<TROWS / 8, 256>>>(x1, tmp, n2s, n2b, out);
}

// round 13
// speedup vs baseline: 2.0467x; 1.4706x over previous
#include <cuda_runtime.h>
#include <cuda_fp16.h>
#include <math.h>
#include <stdint.h>

// ---------------- problem constants ----------------
#define TROWS 131072          // B * H * W = 32 * 4096
#define DIMC  384
#define HIDC  1536
#define QKVC  1152
#define NHEAD 12
#define HDIM  32
#define NTOK  64              // tokens per window
#define NWIN  2048            // 32 * 64 windows

// ---------------- scratch (device globals; no allocation) ----------------
__device__ float  g_qkv[150994944];    // TROWS * 1152 (fp32, attention input)
__device__ float  g_tmp[50331648];     // TROWS * 384
__device__ float  g_x1[50331648];      // TROWS * 384
__device__ __half g_xh[50331648];      // fp16 x
__device__ __half g_attnh[50331648];   // fp16 attention output
__device__ __half g_x1h[50331648];     // fp16 x1
__device__ __half g_hidh[201326592];   // fp16 hidden
__device__ __half g_qkvwh[442368];
__device__ __half g_projwh[147456];
__device__ __half g_fc1wh[589824];
__device__ __half g_fc2wh[589824];
__device__ float  g_bias16[NHEAD * 225];
__device__ float  g_scale[NHEAD];
__device__ float  g_qkvbias[QKVC];

__device__ __forceinline__ uint32_t ph2(float lo, float hi) {
    __half2 h = __floats2half2_rn(lo, hi);
    return *(uint32_t*)&h;
}

// ---------------- fp32 -> fp16 convert ----------------
__global__ void cvt_kernel(const float4* __restrict__ in, uint2* __restrict__ out, int n4) {
    int i = blockIdx.x * blockDim.x + threadIdx.x;
    if (i < n4) {
        float4 v = in[i];
        uint2 o;
        o.x = ph2(v.x, v.y);
        o.y = ph2(v.z, v.w);
        out[i] = o;
    }
}

// ---------------- prep: CPB table, head scales, qkv bias ----------------
__device__ __forceinline__ float cpb_norm(int c) {
    float t = (float)c * (8.0f / 7.0f);
    float s = (t > 0.f) ? 1.f : ((t < 0.f) ? -1.f : 0.f);
    return s * log2f(fabsf(t) + 1.0f) * (1.0f / 3.0f);
}

__global__ void prep_kernel(const float* __restrict__ ls,
                            const float* __restrict__ w1,
                            const float* __restrict__ b1,
                            const float* __restrict__ w2,
                            const float* __restrict__ qb,
                            const float* __restrict__ vb)
{
    int tid = threadIdx.x;
    for (int i = tid; i < QKVC; i += 256) {
        float v = 0.f;
        if (i < 384) v = qb[i];
        else if (i >= 768) v = vb[i - 768];
        g_qkvbias[i] = v;
    }
    if (tid < NHEAD) g_scale[tid] = expf(fminf(ls[tid], 4.6051701859880914f)); // ln(100)
    if (tid < 225) {
        int i = tid / 15, j = tid % 15;
        float f0 = cpb_norm(j - 7);
        float f1 = cpb_norm(i - 7);
        float acc[NHEAD];
        #pragma unroll
        for (int h = 0; h < NHEAD; h++) acc[h] = 0.f;
        for (int u = 0; u < 512; u++) {
            float hu = fmaf(f0, w1[u], fmaf(f1, w1[512 + u], b1[u]));
            hu = fmaxf(hu, 0.f);
            #pragma unroll
            for (int h = 0; h < NHEAD; h++) acc[h] = fmaf(hu, w2[u * 12 + h], acc[h]);
        }
        #pragma unroll
        for (int h = 0; h < NHEAD; h++)
            g_bias16[h * 225 + tid] = 16.f / (1.f + expf(-acc[h]));
    }
}

// ---------------- attention: one (window, head) per block, fp16 out ----------------
__global__ __launch_bounds__(64) void attn_kernel(const float* __restrict__ qkv,
                                                  __half* __restrict__ out)
{
    __shared__ float kn[64][33];
    __shared__ float vs[64][33];
    __shared__ float bia[225];
    __shared__ int   lab[64];

    int blk  = blockIdx.x;
    int head = blk % NHEAD;
    int w    = blk / NHEAD;
    int b    = w >> 6;
    int win  = w & 63;
    int wh = win >> 3, ww = win & 7;
    int t = threadIdx.x;
    int r = t >> 3, c = t & 7;
    int hp = wh * 8 + r, wp = ww * 8 + c;
    int sh = (hp + 4) & 63, sw = (wp + 4) & 63;
    size_t row = (size_t)b * 4096 + (size_t)sh * 64 + sw;
    const float* base = qkv + row * QKVC + head * HDIM;

    int lh = (hp < 56) ? 0 : ((hp < 60) ? 1 : 2);
    int lw = (wp < 56) ? 0 : ((wp < 60) ? 1 : 2);
    lab[t] = lh * 3 + lw;

    for (int i = t; i < 225; i += 64) bia[i] = g_bias16[head * 225 + i];

    float qreg[HDIM];
    {
        float tmp[HDIM];
        float nk = 0.f;
        #pragma unroll
        for (int d4 = 0; d4 < 8; d4++) {
            float4 v4 = *(const float4*)(base + 384 + d4 * 4);
            tmp[d4*4+0] = v4.x; tmp[d4*4+1] = v4.y; tmp[d4*4+2] = v4.z; tmp[d4*4+3] = v4.w;
        }
        #pragma unroll
        for (int d = 0; d < HDIM; d++) nk = fmaf(tmp[d], tmp[d], nk);
        float invk = 1.0f / sqrtf(nk);
        #pragma unroll
        for (int d = 0; d < HDIM; d++) kn[t][d] = tmp[d] * invk;

        #pragma unroll
        for (int d4 = 0; d4 < 8; d4++) {
            float4 v4 = *(const float4*)(base + 768 + d4 * 4);
            vs[t][d4*4+0] = v4.x; vs[t][d4*4+1] = v4.y; vs[t][d4*4+2] = v4.z; vs[t][d4*4+3] = v4.w;
        }

        float nq = 0.f;
        #pragma unroll
        for (int d4 = 0; d4 < 8; d4++) {
            float4 v4 = *(const float4*)(base + d4 * 4);
            qreg[d4*4+0] = v4.x; qreg[d4*4+1] = v4.y; qreg[d4*4+2] = v4.z; qreg[d4*4+3] = v4.w;
        }
        #pragma unroll
        for (int d = 0; d < HDIM; d++) nq = fmaf(qreg[d], qreg[d], nq);
        float invq = g_scale[head] / sqrtf(nq);
        #pragma unroll
        for (int d = 0; d < HDIM; d++) qreg[d] *= invq;
    }
    __syncthreads();

    float lg[NTOK];
    float mx = -1e30f;
    int myl = lab[t];
    for (int t2 = 0; t2 < NTOK; t2++) {
        float acc = 0.f;
        #pragma unroll
        for (int d = 0; d < HDIM; d++) acc = fmaf(qreg[d], kn[t2][d], acc);
        int r2 = t2 >> 3, c2 = t2 & 7;
        acc += bia[(c - c2 + 7) * 15 + (r - r2 + 7)];
        if (myl != lab[t2]) acc -= 100.f;
        lg[t2] = acc;
        mx = fmaxf(mx, acc);
    }
    float ssum = 0.f;
    for (int t2 = 0; t2 < NTOK; t2++) {
        lg[t2] = __expf(lg[t2] - mx);
        ssum += lg[t2];
    }
    float isum = 1.0f / ssum;
    for (int t2 = 0; t2 < NTOK; t2++) lg[t2] *= isum;

    __half* orow = out + row * DIMC + head * HDIM;
    for (int d = 0; d < HDIM; d += 2) {
        float a0 = 0.f, a1 = 0.f;
        for (int t2 = 0; t2 < NTOK; t2++) {
            a0 = fmaf(lg[t2], vs[t2][d], a0);
            a1 = fmaf(lg[t2], vs[t2][d + 1], a1);
        }
        *(__half2*)(orow + d) = __floats2half2_rn(a0, a1);
    }
}

// ================ fp16 GEMM: cp.async staging + ldmatrix + mma.m16n8k16 ================
// A fp16 [M,K] row-major, B fp16 [K,N] row-major. CTA 128x128, BK=32,
// 8 warps of 64x32, double-buffered. A smem stride 80B, B smem stride 272B
// (ldmatrix conflict-free, layouts proven in R12).

#define ASTRB 80
#define BSTRB 272

__device__ __forceinline__ void cpa16(uint32_t dst, const void* src) {
    asm volatile("cp.async.cg.shared.global [%0], [%1], 16;" :: "r"(dst), "l"(src));
}

__device__ __forceinline__ void ldsm_x4(uint32_t* r, uint32_t addr) {
    asm volatile("ldmatrix.sync.aligned.m8n8.x4.shared.b16 {%0,%1,%2,%3}, [%4];"
                 : "=r"(r[0]), "=r"(r[1]), "=r"(r[2]), "=r"(r[3]) : "r"(addr));
}

__device__ __forceinline__ void ldsm_x2t(uint32_t* r, uint32_t addr) {
    asm volatile("ldmatrix.sync.aligned.m8n8.x2.trans.shared.b16 {%0,%1}, [%2];"
                 : "=r"(r[0]), "=r"(r[1]) : "r"(addr));
}

__device__ __forceinline__ void mma_f16(float* d, const uint32_t* a, const uint32_t* b) {
    asm volatile(
        "mma.sync.aligned.m16n8k16.row.col.f32.f16.f16.f32 "
        "{%0,%1,%2,%3}, {%4,%5,%6,%7}, {%8,%9}, {%0,%1,%2,%3};"
        : "+f"(d[0]), "+f"(d[1]), "+f"(d[2]), "+f"(d[3])
        : "r"(a[0]), "r"(a[1]), "r"(a[2]), "r"(a[3]), "r"(b[0]), "r"(b[1]));
}

template<int ACT, int OUT16>
__global__ __launch_bounds__(256, 2) void hgemm_kernel(
    const __half* __restrict__ A, const __half* __restrict__ B,
    const float* __restrict__ bias, void* __restrict__ Cv,
    int M, int N, int K)
{
    __shared__ __align__(16) char Asm[2][128 * ASTRB];   // 2 x 10240 B
    __shared__ __align__(16) char Bsm[2][32 * BSTRB];    // 2 x 8704 B

    int tid = threadIdx.x;
    int lane = tid & 31, wid = tid >> 5;
    int wm = (wid & 1) * 64;
    int wn = (wid >> 1) * 32;
    int bm = blockIdx.y * 128, bn = blockIdx.x * 128;

    // ---- cp.async staging assignment ----
    int a_m = tid >> 1, a_h = tid & 1;                  // A: row, k-half(16)
    const __half* Ap = A + (size_t)(bm + a_m) * K + a_h * 16;
    uint32_t a_dst = (uint32_t)(a_m * ASTRB + a_h * 32);
    int b_k = tid >> 3, b_c = tid & 7;                  // B: k-row, 16-n chunk
    const __half* Bp = B + (size_t)b_k * N + bn + b_c * 16;
    uint32_t b_dst = (uint32_t)(b_k * BSTRB + b_c * 32);

    uint32_t As0 = (uint32_t)__cvta_generic_to_shared(&Asm[0][0]);
    uint32_t As1 = (uint32_t)__cvta_generic_to_shared(&Asm[1][0]);
    uint32_t Bs0 = (uint32_t)__cvta_generic_to_shared(&Bsm[0][0]);
    uint32_t Bs1 = (uint32_t)__cvta_generic_to_shared(&Bsm[1][0]);

    // ---- fragment lane addressing (identical to proven R12) ----
    int rowA = wm + ((lane >> 3) & 1) * 8 + (lane & 7);
    int colA = lane >> 4;
    int rowB = lane & 15;

    float acc[4][4][4];
#pragma unroll
    for (int i = 0; i < 4; i++)
#pragma unroll
        for (int j = 0; j < 4; j++)
#pragma unroll
            for (int l = 0; l < 4; l++) acc[i][j][l] = 0.f;

    auto stage = [&](int kt, int bf) {
        uint32_t ad = (bf ? As1 : As0) + a_dst;
        const __half* as = Ap + kt * 32;
        cpa16(ad, as);
        cpa16(ad + 16, as + 8);
        uint32_t bd = (bf ? Bs1 : Bs0) + b_dst;
        const __half* bs = Bp + (size_t)(kt * 32) * N;
        cpa16(bd, bs);
        cpa16(bd + 16, bs + 8);
        asm volatile("cp.async.commit_group;" ::: "memory");
    };

    stage(0, 0);

    int nk = K >> 5;
    for (int kt = 0; kt < nk; kt++) {
        int cur = kt & 1;
        if (kt + 1 < nk) {
            stage(kt + 1, cur ^ 1);
            asm volatile("cp.async.wait_group 1;" ::: "memory");
        } else {
            asm volatile("cp.async.wait_group 0;" ::: "memory");
        }
        __syncthreads();

        uint32_t Abase = (cur ? As1 : As0) + (uint32_t)(rowA * ASTRB + colA * 16);
        uint32_t Bbase = (cur ? Bs1 : Bs0) + (uint32_t)(rowB * BSTRB + wn * 2);
#pragma unroll
        for (int ks = 0; ks < 2; ks++) {
            uint32_t af[4][4], bf[4][2];
#pragma unroll
            for (int mi = 0; mi < 4; mi++)
                ldsm_x4(af[mi], Abase + mi * (16 * ASTRB) + ks * 32);
#pragma unroll
            for (int ni = 0; ni < 4; ni++)
                ldsm_x2t(bf[ni], Bbase + ks * (16 * BSTRB) + ni * 16);
#pragma unroll
            for (int mi = 0; mi < 4; mi++)
#pragma unroll
                for (int ni = 0; ni < 4; ni++)
                    mma_f16(acc[mi][ni], af[mi], bf[ni]);
        }
        __syncthreads();
    }

    // ---- epilogue ----
    int lk = lane & 3, lm = lane >> 2;
#pragma unroll
    for (int mi = 0; mi < 4; mi++) {
#pragma unroll
        for (int part = 0; part < 2; part++) {
            int row = bm + wm + mi * 16 + lm + part * 8;
#pragma unroll
            for (int ni = 0; ni < 4; ni++) {
                int col = bn + wn + ni * 8 + lk * 2;
                float v0 = acc[mi][ni][part * 2 + 0] + bias[col];
                float v1 = acc[mi][ni][part * 2 + 1] + bias[col + 1];
                if (ACT == 1) {
                    float i0 = fmaf(0.044715f * v0 * v0, v0, v0);
                    v0 = 0.5f * v0 * (1.f + tanhf(0.7978845608028654f * i0));
                    float i1 = fmaf(0.044715f * v1 * v1, v1, v1);
                    v1 = 0.5f * v1 * (1.f + tanhf(0.7978845608028654f * i1));
                }
                if (OUT16) {
                    __half* Ch = (__half*)Cv;
                    *(__half2*)(Ch + (size_t)row * N + col) = __floats2half2_rn(v0, v1);
                } else {
                    float* Cf = (float*)Cv;
                    *(float2*)(Cf + (size_t)row * N + col) = make_float2(v0, v1);
                }
            }
        }
    }
}

// ---------------- residual + LayerNorm (warp per row, optional fp16 copy) ----------------
template<int WH>
__global__ __launch_bounds__(256) void add_ln_kernel(
    const float* __restrict__ res, const float* __restrict__ y,
    const float* __restrict__ sc, const float* __restrict__ bi,
    float* __restrict__ out, __half* __restrict__ outh)
{
    int row  = blockIdx.x * 8 + (threadIdx.x >> 5);
    int lane = threadIdx.x & 31;
    const float* yr = y + (size_t)row * DIMC;
    float v[12];
    float s = 0.f, s2 = 0.f;
    #pragma unroll
    for (int k = 0; k < 12; k++) {
        v[k] = yr[lane + k * 32];
        s += v[k];
        s2 = fmaf(v[k], v[k], s2);
    }
    #pragma unroll
    for (int o = 16; o > 0; o >>= 1) {
        s  += __shfl_xor_sync(0xffffffffu, s,  o);
        s2 += __shfl_xor_sync(0xffffffffu, s2, o);
    }
    float mu  = s * (1.f / 384.f);
    float var = s2 * (1.f / 384.f) - mu * mu;
    float inv = rsqrtf(var + 1e-6f);
    const float* rr = res + (size_t)row * DIMC;
    float* orow = out + (size_t)row * DIMC;
    __half* hrow = WH ? (outh + (size_t)row * DIMC) : (__half*)0;
    #pragma unroll
    for (int k = 0; k < 12; k++) {
        int col = lane + k * 32;
        float o = rr[col] + (v[k] - mu) * inv * sc[col] + bi[col];
        orow[col] = o;
        if (WH) hrow[col] = __float2half(o);
    }
}

// ---------------- launch ----------------
extern "C" void kernel_launch(void* const* d_in, const int* in_sizes, int n_in,
                              void* d_out, int out_size)
{
    (void)in_sizes; (void)n_in; (void)out_size;
    const float* x        = (const float*)d_in[0];
    const float* qkv_w    = (const float*)d_in[1];
    const float* q_bias   = (const float*)d_in[2];
    const float* v_bias   = (const float*)d_in[3];
    const float* lscale   = (const float*)d_in[4];
    const float* cpb_w1   = (const float*)d_in[5];
    const float* cpb_b1   = (const float*)d_in[6];
    const float* cpb_w2   = (const float*)d_in[7];
    const float* proj_w   = (const float*)d_in[8];
    const float* proj_b   = (const float*)d_in[9];
    const float* n1s      = (const float*)d_in[10];
    const float* n1b      = (const float*)d_in[11];
    const float* fc1_w    = (const float*)d_in[12];
    const float* fc1_b    = (const float*)d_in[13];
    const float* fc2_w    = (const float*)d_in[14];
    const float* fc2_b    = (const float*)d_in[15];
    const float* n2s      = (const float*)d_in[16];
    const float* n2b      = (const float*)d_in[17];
    float* out = (float*)d_out;

    float *qkv, *tmp, *x1, *qbias;
    __half *xh, *attnh, *x1h, *hidh, *qkvwh, *projwh, *fc1wh, *fc2wh;
    cudaGetSymbolAddress((void**)&qkv,    g_qkv);
    cudaGetSymbolAddress((void**)&tmp,    g_tmp);
    cudaGetSymbolAddress((void**)&x1,     g_x1);
    cudaGetSymbolAddress((void**)&qbias,  g_qkvbias);
    cudaGetSymbolAddress((void**)&xh,     g_xh);
    cudaGetSymbolAddress((void**)&attnh,  g_attnh);
    cudaGetSymbolAddress((void**)&x1h,    g_x1h);
    cudaGetSymbolAddress((void**)&hidh,   g_hidh);
    cudaGetSymbolAddress((void**)&qkvwh,  g_qkvwh);
    cudaGetSymbolAddress((void**)&projwh, g_projwh);
    cudaGetSymbolAddress((void**)&fc1wh,  g_fc1wh);
    cudaGetSymbolAddress((void**)&fc2wh,  g_fc2wh);

    prep_kernel<<<1, 256>>>(lscale, cpb_w1, cpb_b1, cpb_w2, q_bias, v_bias);

    // fp16 conversions (x + all weights)
    cvt_kernel<<<(50331648/4 + 255)/256, 256>>>((const float4*)x, (uint2*)xh, 50331648/4);
    cvt_kernel<<<(442368/4 + 255)/256, 256>>>((const float4*)qkv_w, (uint2*)qkvwh, 442368/4);
    cvt_kernel<<<(147456/4 + 255)/256, 256>>>((const float4*)proj_w, (uint2*)projwh, 147456/4);
    cvt_kernel<<<(589824/4 + 255)/256, 256>>>((const float4*)fc1_w, (uint2*)fc1wh, 589824/4);
    cvt_kernel<<<(589824/4 + 255)/256, 256>>>((const float4*)fc2_w, (uint2*)fc2wh, 589824/4);

    // qkv = x @ qkv_w + [q_bias, 0, v_bias]  (fp32 out for attention)
    {
        dim3 grid(QKVC / 128, TROWS / 128);
        hgemm_kernel<0, 0><<<grid, 256>>>(xh, qkvwh, qbias, qkv, TROWS, QKVC, DIMC);
    }

    // windowed cosine attention -> fp16
    attn_kernel<<<NWIN * NHEAD, 64>>>(qkv, attnh);

    // proj (fp32 out)
    {
        dim3 grid(DIMC / 128, TROWS / 128);
        hgemm_kernel<0, 0><<<grid, 256>>>(attnh, projwh, proj_b, tmp, TROWS, DIMC, DIMC);
    }

    // x1 = x + LN(proj_out), dual-write fp16
    add_ln_kernel<1><<<TROWS / 8, 256>>>(x, tmp, n1s, n1b, x1, x1h);

    // hid = gelu(x1 @ fc1_w + fc1_b) -> fp16
    {
        dim3 grid(HIDC / 128, TROWS / 128);
        hgemm_kernel<1, 1><<<grid, 256>>>(x1h, fc1wh, fc1_b, hidh, TROWS, HIDC, DIMC);
    }

    // y = hid @ fc2_w + fc2_b (fp32 out)
    {
        dim3 grid(DIMC / 128, TROWS / 128);
        hgemm_kernel<0, 0><<<grid, 256>>>(hidh, fc2wh, fc2_b, tmp, TROWS, DIMC, HIDC);
    }

    // out = x1 + LN(y)
    add_ln_kernel<0><<<TROWS / 8, 256>>>(x1, tmp, n2s, n2b, out, (__half*)0);
}

// round 14
// speedup vs baseline: 2.0870x; 1.0197x over previous
#include <cuda_runtime.h>
#include <cuda_fp16.h>
#include <math.h>
#include <stdint.h>

// ---------------- problem constants ----------------
#define TROWS 131072          // B * H * W = 32 * 4096
#define DIMC  384
#define HIDC  1536
#define QKVC  1152
#define NHEAD 12
#define HDIM  32
#define NTOK  64              // tokens per window
#define NWIN  2048            // 32 * 64 windows

// ---------------- scratch (device globals; no allocation) ----------------
__device__ float  g_tmp[50331648];     // TROWS * 384
__device__ float  g_x1[50331648];      // TROWS * 384
__device__ __half g_qkvh[150994944];   // fp16 qkv
__device__ __half g_xh[50331648];      // fp16 x
__device__ __half g_attnh[50331648];   // fp16 attention output
__device__ __half g_x1h[50331648];     // fp16 x1
__device__ __half g_hidh[201326592];   // fp16 hidden
__device__ __half g_qkvwh[442368];
__device__ __half g_projwh[147456];
__device__ __half g_fc1wh[589824];
__device__ __half g_fc2wh[589824];
__device__ float  g_bias16[NHEAD * 225];
__device__ float  g_scale[NHEAD];
__device__ float  g_qkvbias[QKVC];

__device__ __forceinline__ uint32_t ph2(float lo, float hi) {
    __half2 h = __floats2half2_rn(lo, hi);
    return *(uint32_t*)&h;
}

// ---------------- fp32 -> fp16 convert ----------------
__global__ void cvt_kernel(const float4* __restrict__ in, uint2* __restrict__ out, int n4) {
    int i = blockIdx.x * blockDim.x + threadIdx.x;
    if (i < n4) {
        float4 v = in[i];
        uint2 o;
        o.x = ph2(v.x, v.y);
        o.y = ph2(v.z, v.w);
        out[i] = o;
    }
}

// ---------------- prep: CPB table, head scales, qkv bias ----------------
__device__ __forceinline__ float cpb_norm(int c) {
    float t = (float)c * (8.0f / 7.0f);
    float s = (t > 0.f) ? 1.f : ((t < 0.f) ? -1.f : 0.f);
    return s * log2f(fabsf(t) + 1.0f) * (1.0f / 3.0f);
}

__global__ void prep_kernel(const float* __restrict__ ls,
                            const float* __restrict__ w1,
                            const float* __restrict__ b1,
                            const float* __restrict__ w2,
                            const float* __restrict__ qb,
                            const float* __restrict__ vb)
{
    int tid = threadIdx.x;
    for (int i = tid; i < QKVC; i += 256) {
        float v = 0.f;
        if (i < 384) v = qb[i];
        else if (i >= 768) v = vb[i - 768];
        g_qkvbias[i] = v;
    }
    if (tid < NHEAD) g_scale[tid] = expf(fminf(ls[tid], 4.6051701859880914f)); // ln(100)
    if (tid < 225) {
        int i = tid / 15, j = tid % 15;
        float f0 = cpb_norm(j - 7);
        float f1 = cpb_norm(i - 7);
        float acc[NHEAD];
        #pragma unroll
        for (int h = 0; h < NHEAD; h++) acc[h] = 0.f;
        for (int u = 0; u < 512; u++) {
            float hu = fmaf(f0, w1[u], fmaf(f1, w1[512 + u], b1[u]));
            hu = fmaxf(hu, 0.f);
            #pragma unroll
            for (int h = 0; h < NHEAD; h++) acc[h] = fmaf(hu, w2[u * 12 + h], acc[h]);
        }
        #pragma unroll
        for (int h = 0; h < NHEAD; h++)
            g_bias16[h * 225 + tid] = 16.f / (1.f + expf(-acc[h]));
    }
}

// ---------------- attention: one (window, head) per block, fp16 in/out ----------------
__global__ __launch_bounds__(64) void attn_kernel(const __half* __restrict__ qkv,
                                                  __half* __restrict__ out)
{
    __shared__ float kn[64][33];
    __shared__ float vs[64][33];
    __shared__ float bia[225];
    __shared__ int   lab[64];

    int blk  = blockIdx.x;
    int head = blk % NHEAD;
    int w    = blk / NHEAD;
    int b    = w >> 6;
    int win  = w & 63;
    int wh = win >> 3, ww = win & 7;
    int t = threadIdx.x;
    int r = t >> 3, c = t & 7;
    int hp = wh * 8 + r, wp = ww * 8 + c;
    int sh = (hp + 4) & 63, sw = (wp + 4) & 63;
    size_t row = (size_t)b * 4096 + (size_t)sh * 64 + sw;
    const __half* base = qkv + row * QKVC + head * HDIM;

    int lh = (hp < 56) ? 0 : ((hp < 60) ? 1 : 2);
    int lw = (wp < 56) ? 0 : ((wp < 60) ? 1 : 2);
    lab[t] = lh * 3 + lw;

    for (int i = t; i < 225; i += 64) bia[i] = g_bias16[head * 225 + i];

    float qreg[HDIM];
    {
        float tmp[HDIM];
        float nk = 0.f;
        #pragma unroll
        for (int d8 = 0; d8 < 4; d8++) {      // K: 32 halves = 4 x uint4
            uint4 u = *(const uint4*)(base + 384 + d8 * 8);
            const __half2* hp2 = (const __half2*)&u;
            #pragma unroll
            for (int q = 0; q < 4; q++) {
                float2 f = __half22float2(hp2[q]);
                tmp[d8*8 + q*2]     = f.x;
                tmp[d8*8 + q*2 + 1] = f.y;
            }
        }
        #pragma unroll
        for (int d = 0; d < HDIM; d++) nk = fmaf(tmp[d], tmp[d], nk);
        float invk = 1.0f / sqrtf(nk);
        #pragma unroll
        for (int d = 0; d < HDIM; d++) kn[t][d] = tmp[d] * invk;

        #pragma unroll
        for (int d8 = 0; d8 < 4; d8++) {      // V
            uint4 u = *(const uint4*)(base + 768 + d8 * 8);
            const __half2* hp2 = (const __half2*)&u;
            #pragma unroll
            for (int q = 0; q < 4; q++) {
                float2 f = __half22float2(hp2[q]);
                vs[t][d8*8 + q*2]     = f.x;
                vs[t][d8*8 + q*2 + 1] = f.y;
            }
        }

        float nq = 0.f;
        #pragma unroll
        for (int d8 = 0; d8 < 4; d8++) {      // Q
            uint4 u = *(const uint4*)(base + d8 * 8);
            const __half2* hp2 = (const __half2*)&u;
            #pragma unroll
            for (int q = 0; q < 4; q++) {
                float2 f = __half22float2(hp2[q]);
                qreg[d8*8 + q*2]     = f.x;
                qreg[d8*8 + q*2 + 1] = f.y;
            }
        }
        #pragma unroll
        for (int d = 0; d < HDIM; d++) nq = fmaf(qreg[d], qreg[d], nq);
        float invq = g_scale[head] / sqrtf(nq);
        #pragma unroll
        for (int d = 0; d < HDIM; d++) qreg[d] *= invq;
    }
    __syncthreads();

    float lg[NTOK];
    float mx = -1e30f;
    int myl = lab[t];
    for (int t2 = 0; t2 < NTOK; t2++) {
        float acc = 0.f;
        #pragma unroll
        for (int d = 0; d < HDIM; d++) acc = fmaf(qreg[d], kn[t2][d], acc);
        int r2 = t2 >> 3, c2 = t2 & 7;
        acc += bia[(c - c2 + 7) * 15 + (r - r2 + 7)];
        if (myl != lab[t2]) acc -= 100.f;
        lg[t2] = acc;
        mx = fmaxf(mx, acc);
    }
    float ssum = 0.f;
    for (int t2 = 0; t2 < NTOK; t2++) {
        lg[t2] = __expf(lg[t2] - mx);
        ssum += lg[t2];
    }
    float isum = 1.0f / ssum;
    for (int t2 = 0; t2 < NTOK; t2++) lg[t2] *= isum;

    __half* orow = out + row * DIMC + head * HDIM;
    for (int d = 0; d < HDIM; d += 2) {
        float a0 = 0.f, a1 = 0.f;
        for (int t2 = 0; t2 < NTOK; t2++) {
            a0 = fmaf(lg[t2], vs[t2][d], a0);
            a1 = fmaf(lg[t2], vs[t2][d + 1], a1);
        }
        *(__half2*)(orow + d) = __floats2half2_rn(a0, a1);
    }
}

// ================ fp16 GEMM: 3-stage cp.async + ldmatrix + mma.m16n8k16 ================
// A fp16 [M,K] row-major, B fp16 [K,N] row-major. CTA 128x128, BK=32,
// 8 warps of 64x32. A smem stride 80B, B smem stride 272B (proven layouts).
// Single __syncthreads per ktile (multistage rule: buffer rewritten 3 iters
// after last read with >=1 barrier between).

#define ASTRB 80
#define BSTRB 272

__device__ __forceinline__ void cpa16(uint32_t dst, const void* src) {
    asm volatile("cp.async.cg.shared.global [%0], [%1], 16;" :: "r"(dst), "l"(src));
}

__device__ __forceinline__ void ldsm_x4(uint32_t* r, uint32_t addr) {
    asm volatile("ldmatrix.sync.aligned.m8n8.x4.shared.b16 {%0,%1,%2,%3}, [%4];"
                 : "=r"(r[0]), "=r"(r[1]), "=r"(r[2]), "=r"(r[3]) : "r"(addr));
}

__device__ __forceinline__ void ldsm_x2t(uint32_t* r, uint32_t addr) {
    asm volatile("ldmatrix.sync.aligned.m8n8.x2.trans.shared.b16 {%0,%1}, [%2];"
                 : "=r"(r[0]), "=r"(r[1]) : "r"(addr));
}

__device__ __forceinline__ void mma_f16(float* d, const uint32_t* a, const uint32_t* b) {
    asm volatile(
        "mma.sync.aligned.m16n8k16.row.col.f32.f16.f16.f32 "
        "{%0,%1,%2,%3}, {%4,%5,%6,%7}, {%8,%9}, {%0,%1,%2,%3};"
        : "+f"(d[0]), "+f"(d[1]), "+f"(d[2]), "+f"(d[3])
        : "r"(a[0]), "r"(a[1]), "r"(a[2]), "r"(a[3]), "r"(b[0]), "r"(b[1]));
}

template<int ACT, int OUT16>
__global__ __launch_bounds__(256, 2) void hgemm_kernel(
    const __half* __restrict__ A, const __half* __restrict__ B,
    const float* __restrict__ bias, void* __restrict__ Cv,
    int M, int N, int K)
{
    __shared__ __align__(16) char Asm[3][128 * ASTRB];   // 3 x 10240 B
    __shared__ __align__(16) char Bsm[3][32 * BSTRB];    // 3 x 8704 B

    int tid = threadIdx.x;
    int lane = tid & 31, wid = tid >> 5;
    int wm = (wid & 1) * 64;
    int wn = (wid >> 1) * 32;
    int bm = blockIdx.y * 128, bn = blockIdx.x * 128;

    // ---- cp.async staging assignment ----
    int a_m = tid >> 1, a_h = tid & 1;                  // A: row, k-half(16)
    const __half* Ap = A + (size_t)(bm + a_m) * K + a_h * 16;
    uint32_t a_dst = (uint32_t)(a_m * ASTRB + a_h * 32);
    int b_k = tid >> 3, b_c = tid & 7;                  // B: k-row, 16-n chunk
    const __half* Bp = B + (size_t)b_k * N + bn + b_c * 16;
    uint32_t b_dst = (uint32_t)(b_k * BSTRB + b_c * 32);

    uint32_t AsB[3], BsB[3];
#pragma unroll
    for (int s = 0; s < 3; s++) {
        AsB[s] = (uint32_t)__cvta_generic_to_shared(&Asm[s][0]);
        BsB[s] = (uint32_t)__cvta_generic_to_shared(&Bsm[s][0]);
    }

    // ---- fragment lane addressing (proven R12) ----
    int rowA = wm + ((lane >> 3) & 1) * 8 + (lane & 7);
    int colA = lane >> 4;
    int rowB = lane & 15;

    float acc[4][4][4];
#pragma unroll
    for (int i = 0; i < 4; i++)
#pragma unroll
        for (int j = 0; j < 4; j++)
#pragma unroll
            for (int l = 0; l < 4; l++) acc[i][j][l] = 0.f;

    auto stage = [&](int kt, int bf) {
        uint32_t ad = AsB[bf] + a_dst;
        const __half* as = Ap + kt * 32;
        cpa16(ad, as);
        cpa16(ad + 16, as + 8);
        uint32_t bd = BsB[bf] + b_dst;
        const __half* bs = Bp + (size_t)(kt * 32) * N;
        cpa16(bd, bs);
        cpa16(bd + 16, bs + 8);
        asm volatile("cp.async.commit_group;" ::: "memory");
    };

    int nk = K >> 5;
    stage(0, 0);
    if (nk > 1) stage(1, 1);

    for (int kt = 0; kt < nk; kt++) {
        int cur = kt % 3;
        if (kt + 1 < nk) {
            asm volatile("cp.async.wait_group 1;" ::: "memory");
        } else {
            asm volatile("cp.async.wait_group 0;" ::: "memory");
        }
        __syncthreads();
        if (kt + 2 < nk) stage(kt + 2, (kt + 2) % 3);

        uint32_t Abase = AsB[cur] + (uint32_t)(rowA * ASTRB + colA * 16);
        uint32_t Bbase = BsB[cur] + (uint32_t)(rowB * BSTRB + wn * 2);
#pragma unroll
        for (int ks = 0; ks < 2; ks++) {
            uint32_t af[4][4], bf[4][2];
#pragma unroll
            for (int mi = 0; mi < 4; mi++)
                ldsm_x4(af[mi], Abase + mi * (16 * ASTRB) + ks * 32);
#pragma unroll
            for (int ni = 0; ni < 4; ni++)
                ldsm_x2t(bf[ni], Bbase + ks * (16 * BSTRB) + ni * 16);
#pragma unroll
            for (int mi = 0; mi < 4; mi++)
#pragma unroll
                for (int ni = 0; ni < 4; ni++)
                    mma_f16(acc[mi][ni], af[mi], bf[ni]);
        }
    }

    // ---- epilogue ----
    int lk = lane & 3, lm = lane >> 2;
#pragma unroll
    for (int mi = 0; mi < 4; mi++) {
#pragma unroll
        for (int part = 0; part < 2; part++) {
            int row = bm + wm + mi * 16 + lm + part * 8;
#pragma unroll
            for (int ni = 0; ni < 4; ni++) {
                int col = bn + wn + ni * 8 + lk * 2;
                float v0 = acc[mi][ni][part * 2 + 0] + bias[col];
                float v1 = acc[mi][ni][part * 2 + 1] + bias[col + 1];
                if (ACT == 1) {
                    float i0 = fmaf(0.044715f * v0 * v0, v0, v0);
                    v0 = 0.5f * v0 * (1.f + tanhf(0.7978845608028654f * i0));
                    float i1 = fmaf(0.044715f * v1 * v1, v1, v1);
                    v1 = 0.5f * v1 * (1.f + tanhf(0.7978845608028654f * i1));
                }
                if (OUT16) {
                    __half* Ch = (__half*)Cv;
                    *(__half2*)(Ch + (size_t)row * N + col) = __floats2half2_rn(v0, v1);
                } else {
                    float* Cf = (float*)Cv;
                    *(float2*)(Cf + (size_t)row * N + col) = make_float2(v0, v1);
                }
            }
        }
    }
}

// ---------------- residual + LayerNorm (warp per row, optional fp16 copy) ----------------
template<int WH>
__global__ __launch_bounds__(256) void add_ln_kernel(
    const float* __restrict__ res, const float* __restrict__ y,
    const float* __restrict__ sc, const float* __restrict__ bi,
    float* __restrict__ out, __half* __restrict__ outh)
{
    int row  = blockIdx.x * 8 + (threadIdx.x >> 5);
    int lane = threadIdx.x & 31;
    const float* yr = y + (size_t)row * DIMC;
    float v[12];
    float s = 0.f, s2 = 0.f;
    #pragma unroll
    for (int k = 0; k < 12; k++) {
        v[k] = yr[lane + k * 32];
        s += v[k];
        s2 = fmaf(v[k], v[k], s2);
    }
    #pragma unroll
    for (int o = 16; o > 0; o >>= 1) {
        s  += __shfl_xor_sync(0xffffffffu, s,  o);
        s2 += __shfl_xor_sync(0xffffffffu, s2, o);
    }
    float mu  = s * (1.f / 384.f);
    float var = s2 * (1.f / 384.f) - mu * mu;
    float inv = rsqrtf(var + 1e-6f);
    const float* rr = res + (size_t)row * DIMC;
    float* orow = out + (size_t)row * DIMC;
    __half* hrow = WH ? (outh + (size_t)row * DIMC) : (__half*)0;
    #pragma unroll
    for (int k = 0; k < 12; k++) {
        int col = lane + k * 32;
        float o = rr[col] + (v[k] - mu) * inv * sc[col] + bi[col];
        orow[col] = o;
        if (WH) hrow[col] = __float2half(o);
    }
}

// ---------------- launch ----------------
extern "C" void kernel_launch(void* const* d_in, const int* in_sizes, int n_in,
                              void* d_out, int out_size)
{
    (void)in_sizes; (void)n_in; (void)out_size;
    const float* x        = (const float*)d_in[0];
    const float* qkv_w    = (const float*)d_in[1];
    const float* q_bias   = (const float*)d_in[2];
    const float* v_bias   = (const float*)d_in[3];
    const float* lscale   = (const float*)d_in[4];
    const float* cpb_w1   = (const float*)d_in[5];
    const float* cpb_b1   = (const float*)d_in[6];
    const float* cpb_w2   = (const float*)d_in[7];
    const float* proj_w   = (const float*)d_in[8];
    const float* proj_b   = (const float*)d_in[9];
    const float* n1s      = (const float*)d_in[10];
    const float* n1b      = (const float*)d_in[11];
    const float* fc1_w    = (const float*)d_in[12];
    const float* fc1_b    = (const float*)d_in[13];
    const float* fc2_w    = (const float*)d_in[14];
    const float* fc2_b    = (const float*)d_in[15];
    const float* n2s      = (const float*)d_in[16];
    const float* n2b      = (const float*)d_in[17];
    float* out = (float*)d_out;

    float *tmp, *x1, *qbias;
    __half *qkvh, *xh, *attnh, *x1h, *hidh, *qkvwh, *projwh, *fc1wh, *fc2wh;
    cudaGetSymbolAddress((void**)&tmp,    g_tmp);
    cudaGetSymbolAddress((void**)&x1,     g_x1);
    cudaGetSymbolAddress((void**)&qbias,  g_qkvbias);
    cudaGetSymbolAddress((void**)&qkvh,   g_qkvh);
    cudaGetSymbolAddress((void**)&xh,     g_xh);
    cudaGetSymbolAddress((void**)&attnh,  g_attnh);
    cudaGetSymbolAddress((void**)&x1h,    g_x1h);
    cudaGetSymbolAddress((void**)&hidh,   g_hidh);
    cudaGetSymbolAddress((void**)&qkvwh,  g_qkvwh);
    cudaGetSymbolAddress((void**)&projwh, g_projwh);
    cudaGetSymbolAddress((void**)&fc1wh,  g_fc1wh);
    cudaGetSymbolAddress((void**)&fc2wh,  g_fc2wh);

    prep_kernel<<<1, 256>>>(lscale, cpb_w1, cpb_b1, cpb_w2, q_bias, v_bias);

    // fp16 conversions (x + all weights)
    cvt_kernel<<<(50331648/4 + 255)/256, 256>>>((const float4*)x, (uint2*)xh, 50331648/4);
    cvt_kernel<<<(442368/4 + 255)/256, 256>>>((const float4*)qkv_w, (uint2*)qkvwh, 442368/4);
    cvt_kernel<<<(147456/4 + 255)/256, 256>>>((const float4*)proj_w, (uint2*)projwh, 147456/4);
    cvt_kernel<<<(589824/4 + 255)/256, 256>>>((const float4*)fc1_w, (uint2*)fc1wh, 589824/4);
    cvt_kernel<<<(589824/4 + 255)/256, 256>>>((const float4*)fc2_w, (uint2*)fc2wh, 589824/4);

    // qkv = x @ qkv_w + [q_bias, 0, v_bias] -> fp16
    {
        dim3 grid(QKVC / 128, TROWS / 128);
        hgemm_kernel<0, 1><<<grid, 256>>>(xh, qkvwh, qbias, qkvh, TROWS, QKVC, DIMC);
    }

    // windowed cosine attention (fp16 in) -> fp16
    attn_kernel<<<NWIN * NHEAD, 64>>>(qkvh, attnh);

    // proj (fp32 out)
    {
        dim3 grid(DIMC / 128, TROWS / 128);
        hgemm_kernel<0, 0><<<grid, 256>>>(attnh, projwh, proj_b, tmp, TROWS, DIMC, DIMC);
    }

    // x1 = x + LN(proj_out), dual-write fp16
    add_ln_kernel<1><<<TROWS / 8, 256>>>(x, tmp, n1s, n1b, x1, x1h);

    // hid = gelu(x1 @ fc1_w + fc1_b) -> fp16
    {
        dim3 grid(HIDC / 128, TROWS / 128);
        hgemm_kernel<1, 1><<<grid, 256>>>(x1h, fc1wh, fc1_b, hidh, TROWS, HIDC, DIMC);
    }

    // y = hid @ fc2_w + fc2_b (fp32 out)
    {
        dim3 grid(DIMC / 128, TROWS / 128);
        hgemm_kernel<0, 0><<<grid, 256>>>(hidh, fc2wh, fc2_b, tmp, TROWS, DIMC, HIDC);
    }

    // out = x1 + LN(y)
    add_ln_kernel<0><<<TROWS / 8, 256>>>(x1, tmp, n2s, n2b, out, (__half*)0);
}